// round 6
// baseline (speedup 1.0000x reference)
#include <cuda_runtime.h>
#include <math.h>
#include <stdint.h>

// ---------------------------------------------------------------------------
// MoELayer: B=65536 tokens, D=256, E=16 experts, H=256, O=256, TOP_K=2
// out = [ y (B*O floats) | p (B*E floats) ]
// ---------------------------------------------------------------------------

#define BATCH   65536
#define DIM     256
#define NEXP    16
#define HID     256
#define OUTD    256
#define GHID    1024   // 4*D

// ---------------- scratch (device globals; no allocations allowed) ----------
__device__ float    g_Y1[(size_t)BATCH * GHID];    // 256 MB gate hidden 1
__device__ float    g_Y2[(size_t)BATCH * DIM];     //  64 MB gate hidden 2
__device__ float    g_w[BATCH * 2];                // renormalized top-2 weights
__device__ int      g_eidx[BATCH * 2];             // top-2 expert ids
__device__ int      g_counts[NEXP];
__device__ int      g_offsets[NEXP + 1];
__device__ int      g_cursor[NEXP];
__device__ unsigned g_list[BATCH * 2];             // entry = token*2 + slot
__device__ float    g_yslots[(size_t)BATCH * 2 * OUTD];  // 128 MB per-slot out

// ---------------------------------------------------------------------------
// k_zero: reset histograms (graph replays need this every iteration)
// ---------------------------------------------------------------------------
__global__ void k_zero() {
    int i = threadIdx.x;
    if (i < NEXP) g_counts[i] = 0;
}

// ---------------------------------------------------------------------------
// Generic fp32 SIMT GEMM: C = relu(A[M,K] @ B[K,N] + bias[N])
// tile 128x256, BK=16, 512 threads, 8x8 per thread.
// Requires M%128==0, N%256==0, K%16==0 (true for all our shapes).
// ---------------------------------------------------------------------------
__global__ __launch_bounds__(512, 1)
void k_gemm_bias_relu(const float* __restrict__ A, const float* __restrict__ B,
                      const float* __restrict__ bv, float* __restrict__ C,
                      int M, int N, int K)
{
    __shared__ float As[16 * 128];
    __shared__ float Bs[16 * 256];

    const int tid = threadIdx.x;
    const int tx = tid & 31;        // n-group (0..31) -> 8 cols each
    const int ty = tid >> 5;        // m-group (0..15) -> 8 rows each
    const int m0 = blockIdx.y * 128;
    const int n0 = blockIdx.x * 256;

    const int a_r = tid >> 2;              // 0..127
    const int a_c = (tid & 3) << 2;        // 0,4,8,12
    const int b_r = tid >> 6;              // 0..7
    const int b_c = (tid & 63) << 2;       // 0..252

    const float* Arow = A + (size_t)(m0 + a_r) * K + a_c;
    const float* Bp   = B + (size_t)b_r * N + n0 + b_c;

    float acc[8][8];
#pragma unroll
    for (int i = 0; i < 8; i++)
#pragma unroll
        for (int j = 0; j < 8; j++) acc[i][j] = 0.f;

    for (int k0 = 0; k0 < K; k0 += 16) {
        float4 av = *(const float4*)(Arow + k0);
        As[(a_c + 0) * 128 + a_r] = av.x;
        As[(a_c + 1) * 128 + a_r] = av.y;
        As[(a_c + 2) * 128 + a_r] = av.z;
        As[(a_c + 3) * 128 + a_r] = av.w;
        *(float4*)&Bs[b_r * 256 + b_c]       = *(const float4*)(Bp + (size_t)k0 * N);
        *(float4*)&Bs[(b_r + 8) * 256 + b_c] = *(const float4*)(Bp + (size_t)(k0 + 8) * N);
        __syncthreads();

#pragma unroll
        for (int kk = 0; kk < 16; kk++) {
            float ar[8], br[8];
            *(float4*)&ar[0] = *(const float4*)&As[kk * 128 + ty * 8];
            *(float4*)&ar[4] = *(const float4*)&As[kk * 128 + ty * 8 + 4];
            *(float4*)&br[0] = *(const float4*)&Bs[kk * 256 + tx * 8];
            *(float4*)&br[4] = *(const float4*)&Bs[kk * 256 + tx * 8 + 4];
#pragma unroll
            for (int i = 0; i < 8; i++)
#pragma unroll
                for (int j = 0; j < 8; j++)
                    acc[i][j] = fmaf(ar[i], br[j], acc[i][j]);
        }
        __syncthreads();
    }

    // epilogue: + bias, relu, store
    float bb[8];
#pragma unroll
    for (int j = 0; j < 8; j++) bb[j] = bv[n0 + tx * 8 + j];
#pragma unroll
    for (int i = 0; i < 8; i++) {
        const int m = m0 + ty * 8 + i;
        float* crow = C + (size_t)m * N + n0 + tx * 8;
        float4 o0, o1;
        o0.x = fmaxf(acc[i][0] + bb[0], 0.f);
        o0.y = fmaxf(acc[i][1] + bb[1], 0.f);
        o0.z = fmaxf(acc[i][2] + bb[2], 0.f);
        o0.w = fmaxf(acc[i][3] + bb[3], 0.f);
        o1.x = fmaxf(acc[i][4] + bb[4], 0.f);
        o1.y = fmaxf(acc[i][5] + bb[5], 0.f);
        o1.z = fmaxf(acc[i][6] + bb[6], 0.f);
        o1.w = fmaxf(acc[i][7] + bb[7], 0.f);
        *(float4*)crow       = o0;
        *(float4*)(crow + 4) = o1;
    }
}

// ---------------------------------------------------------------------------
// k_gate3: one warp per token. logits = Y2 @ g3 + gb3; softmax(T=1);
// top-2 on logits (ties -> lowest index, matching lax.top_k); renormalize;
// write sparse p to output; record (e0,e1,w0,w1); histogram counts.
// grid = 8192 blocks x 256 threads = exactly 65536 warps.
// ---------------------------------------------------------------------------
__global__ void k_gate3(const float* __restrict__ Y2, const float* __restrict__ g3,
                        const float* __restrict__ gb3, float* __restrict__ p_out)
{
    __shared__ float sg3[NEXP * DIM];   // transposed: [e][k]
    __shared__ float sgb3[NEXP];
    for (int i = threadIdx.x; i < NEXP * DIM; i += blockDim.x) {
        int k = i >> 4, e = i & 15;
        sg3[e * DIM + k] = g3[i];
    }
    if (threadIdx.x < NEXP) sgb3[threadIdx.x] = gb3[threadIdx.x];
    __syncthreads();

    const int gw   = (blockIdx.x * blockDim.x + threadIdx.x) >> 5;  // token
    const int lane = threadIdx.x & 31;

    const float* y = Y2 + (size_t)gw * DIM;
    float yv[8];
#pragma unroll
    for (int i = 0; i < 8; i++) yv[i] = y[lane + 32 * i];

    float l[NEXP];
#pragma unroll
    for (int e = 0; e < NEXP; e++) {
        float s = 0.f;
#pragma unroll
        for (int i = 0; i < 8; i++)
            s = fmaf(yv[i], sg3[e * DIM + lane + 32 * i], s);
        l[e] = s;
    }
#pragma unroll
    for (int off = 16; off > 0; off >>= 1)
#pragma unroll
        for (int e = 0; e < NEXP; e++)
            l[e] += __shfl_xor_sync(0xffffffffu, l[e], off);
#pragma unroll
    for (int e = 0; e < NEXP; e++) l[e] += sgb3[e];

    // top-2 on logits (monotonic w.r.t. softmax probs)
    int i1 = 0; float t1 = l[0];
#pragma unroll
    for (int e = 1; e < NEXP; e++) if (l[e] > t1) { t1 = l[e]; i1 = e; }
    int i2 = -1; float t2 = -INFINITY;
#pragma unroll
    for (int e = 0; e < NEXP; e++) if (e != i1 && l[e] > t2) { t2 = l[e]; i2 = e; }

    // softmax values for the two selected experts
    const float mx = t1;
    float se = 0.f;
#pragma unroll
    for (int e = 0; e < NEXP; e++) se += expf(l[e] - mx);
    const float inv = 1.f / se;
    const float v1 = expf(t1 - mx) * inv;
    const float v2 = expf(t2 - mx) * inv;
    const float dn = 1.f / (v1 + v2 + 1e-9f);
    const float w0 = v1 * dn, w1 = v2 * dn;

    if (lane < NEXP) {
        float pv = (lane == i1) ? w0 : ((lane == i2) ? w1 : 0.f);
        p_out[(size_t)gw * NEXP + lane] = pv;
    }
    if (lane == 0) {
        g_w[gw * 2 + 0]    = w0;
        g_w[gw * 2 + 1]    = w1;
        g_eidx[gw * 2 + 0] = i1;
        g_eidx[gw * 2 + 1] = i2;
        atomicAdd(&g_counts[i1], 1);
        atomicAdd(&g_counts[i2], 1);
    }
}

// ---------------------------------------------------------------------------
// k_scan: serial exclusive scan of 16 counts; zero cursors.
// ---------------------------------------------------------------------------
__global__ void k_scan() {
    if (threadIdx.x == 0) {
        int acc = 0;
        for (int i = 0; i < NEXP; i++) {
            g_offsets[i] = acc;
            acc += g_counts[i];
            g_cursor[i] = 0;
        }
        g_offsets[NEXP] = acc;
    }
}

// ---------------------------------------------------------------------------
// k_scatter: bucket entries by expert.
// ---------------------------------------------------------------------------
__global__ void k_scatter() {
    int i = blockIdx.x * blockDim.x + threadIdx.x;   // entry = token*2 + slot
    if (i >= BATCH * 2) return;
    int e = g_eidx[i];
    int pos = atomicAdd(&g_cursor[e], 1);
    g_list[g_offsets[e] + pos] = (unsigned)i;
}

// ---------------------------------------------------------------------------
// k_expert: grouped expert GEMM. Each block = one 128-row tile of one expert.
//   stage 1: H[128,256] = relu((gather(x)+bias[e]) @ W1[e] + b1[e])  -> smem
//   stage 2: OUT[128,256] = (H @ W2[e] + b2[e]) * w  -> g_yslots rows
// dynamic smem: Hs(128x260) + As(16x128) + Bs(16x256) + bias rows + meta
// ---------------------------------------------------------------------------
#define HPAD 260
#define EXPERT_SMEM ((128*HPAD + 16*128 + 16*256 + 3*256 + 128) * 4 + 128 * 4)

__global__ __launch_bounds__(512, 1)
void k_expert(const float* __restrict__ x, const float* __restrict__ bias,
              const float* __restrict__ W1, const float* __restrict__ b1,
              const float* __restrict__ W2, const float* __restrict__ b2)
{
    extern __shared__ float sm[];
    float* Hs     = sm;                         // 128*HPAD
    float* As     = Hs + 128 * HPAD;            // 16*128
    float* Bs     = As + 16 * 128;              // 16*256
    float* s_bias = Bs + 16 * 256;              // 256
    float* s_b1   = s_bias + 256;               // 256
    float* s_b2   = s_b1 + 256;                 // 256
    float* s_w    = s_b2 + 256;                 // 128
    int*   s_ent  = (int*)(s_w + 128);          // 128
    __shared__ int s_meta[3];

    const int tid = threadIdx.x;

    if (tid == 0) {
        int bid = blockIdx.x, acc = 0, e = -1, row0 = 0, cnt = 0;
        for (int i = 0; i < NEXP; i++) {
            int c  = g_counts[i];
            int nt = (c + 127) >> 7;
            if (e < 0 && bid < acc + nt) {
                int tt = bid - acc;
                e = i;
                row0 = g_offsets[i] + tt * 128;
                cnt  = c - tt * 128;
                if (cnt > 128) cnt = 128;
            }
            acc += nt;
        }
        s_meta[0] = e; s_meta[1] = row0; s_meta[2] = cnt;
    }
    __syncthreads();

    const int e = s_meta[0];
    if (e < 0) return;
    const int row0 = s_meta[1];
    const int cnt  = s_meta[2];

    if (tid < 128) {
        unsigned ent = g_list[row0 + ((tid < cnt) ? tid : 0)];
        s_ent[tid] = (int)ent;
        s_w[tid]   = g_w[ent];
    }
    for (int i = tid; i < 256; i += 512) {
        s_bias[i] = bias[e * 256 + i];
        s_b1[i]   = b1[e * 256 + i];
        s_b2[i]   = b2[e * 256 + i];
    }
    __syncthreads();

    const int tx = tid & 31, ty = tid >> 5;
    const int a_r = tid >> 2, a_c = (tid & 3) << 2;
    const int b_r = tid >> 6, b_c = (tid & 63) << 2;

    const int tok = s_ent[a_r] >> 1;
    const float* xrow = x + (size_t)tok * DIM;

    float acc[8][8];
#pragma unroll
    for (int i = 0; i < 8; i++)
#pragma unroll
        for (int j = 0; j < 8; j++) acc[i][j] = 0.f;

    // ------------------ stage 1: H = relu((x+bias) @ W1 + b1) ---------------
    const float* W1e = W1 + (size_t)e * DIM * HID;
    for (int k0 = 0; k0 < DIM; k0 += 16) {
        float4 av = *(const float4*)(xrow + k0 + a_c);
        float4 bb = *(const float4*)(s_bias + k0 + a_c);
        As[(a_c + 0) * 128 + a_r] = av.x + bb.x;
        As[(a_c + 1) * 128 + a_r] = av.y + bb.y;
        As[(a_c + 2) * 128 + a_r] = av.z + bb.z;
        As[(a_c + 3) * 128 + a_r] = av.w + bb.w;
        *(float4*)&Bs[b_r * 256 + b_c]       = *(const float4*)(W1e + (size_t)(k0 + b_r) * HID + b_c);
        *(float4*)&Bs[(b_r + 8) * 256 + b_c] = *(const float4*)(W1e + (size_t)(k0 + b_r + 8) * HID + b_c);
        __syncthreads();
#pragma unroll
        for (int kk = 0; kk < 16; kk++) {
            float ar[8], br[8];
            *(float4*)&ar[0] = *(const float4*)&As[kk * 128 + ty * 8];
            *(float4*)&ar[4] = *(const float4*)&As[kk * 128 + ty * 8 + 4];
            *(float4*)&br[0] = *(const float4*)&Bs[kk * 256 + tx * 8];
            *(float4*)&br[4] = *(const float4*)&Bs[kk * 256 + tx * 8 + 4];
#pragma unroll
            for (int i = 0; i < 8; i++)
#pragma unroll
                for (int j = 0; j < 8; j++)
                    acc[i][j] = fmaf(ar[i], br[j], acc[i][j]);
        }
        __syncthreads();
    }
    // write H tile to smem (relu + b1)
#pragma unroll
    for (int i = 0; i < 8; i++) {
        const int m = ty * 8 + i;
        float4 h0, h1;
        h0.x = fmaxf(acc[i][0] + s_b1[tx * 8 + 0], 0.f);
        h0.y = fmaxf(acc[i][1] + s_b1[tx * 8 + 1], 0.f);
        h0.z = fmaxf(acc[i][2] + s_b1[tx * 8 + 2], 0.f);
        h0.w = fmaxf(acc[i][3] + s_b1[tx * 8 + 3], 0.f);
        h1.x = fmaxf(acc[i][4] + s_b1[tx * 8 + 4], 0.f);
        h1.y = fmaxf(acc[i][5] + s_b1[tx * 8 + 5], 0.f);
        h1.z = fmaxf(acc[i][6] + s_b1[tx * 8 + 6], 0.f);
        h1.w = fmaxf(acc[i][7] + s_b1[tx * 8 + 7], 0.f);
        *(float4*)&Hs[m * HPAD + tx * 8]     = h0;
        *(float4*)&Hs[m * HPAD + tx * 8 + 4] = h1;
    }
    __syncthreads();

    // ------------------ stage 2: OUT = (H @ W2 + b2) * w --------------------
#pragma unroll
    for (int i = 0; i < 8; i++)
#pragma unroll
        for (int j = 0; j < 8; j++) acc[i][j] = 0.f;

    const float* W2e = W2 + (size_t)e * HID * OUTD;
    for (int k0 = 0; k0 < HID; k0 += 16) {
        *(float4*)&Bs[b_r * 256 + b_c]       = *(const float4*)(W2e + (size_t)(k0 + b_r) * OUTD + b_c);
        *(float4*)&Bs[(b_r + 8) * 256 + b_c] = *(const float4*)(W2e + (size_t)(k0 + b_r + 8) * OUTD + b_c);
        __syncthreads();
#pragma unroll
        for (int kk = 0; kk < 16; kk++) {
            float ar[8], br[8];
#pragma unroll
            for (int i = 0; i < 8; i++)
                ar[i] = Hs[(ty * 8 + i) * HPAD + k0 + kk];   // warp-broadcast
            *(float4*)&br[0] = *(const float4*)&Bs[kk * 256 + tx * 8];
            *(float4*)&br[4] = *(const float4*)&Bs[kk * 256 + tx * 8 + 4];
#pragma unroll
            for (int i = 0; i < 8; i++)
#pragma unroll
                for (int j = 0; j < 8; j++)
                    acc[i][j] = fmaf(ar[i], br[j], acc[i][j]);
        }
        __syncthreads();
    }

#pragma unroll
    for (int i = 0; i < 8; i++) {
        const int m = ty * 8 + i;
        if (m < cnt) {
            const unsigned ent = (unsigned)s_ent[m];
            const float w = s_w[m];
            float* dst = g_yslots + (size_t)ent * OUTD + tx * 8;
            float4 o0, o1;
            o0.x = (acc[i][0] + s_b2[tx * 8 + 0]) * w;
            o0.y = (acc[i][1] + s_b2[tx * 8 + 1]) * w;
            o0.z = (acc[i][2] + s_b2[tx * 8 + 2]) * w;
            o0.w = (acc[i][3] + s_b2[tx * 8 + 3]) * w;
            o1.x = (acc[i][4] + s_b2[tx * 8 + 4]) * w;
            o1.y = (acc[i][5] + s_b2[tx * 8 + 5]) * w;
            o1.z = (acc[i][6] + s_b2[tx * 8 + 6]) * w;
            o1.w = (acc[i][7] + s_b2[tx * 8 + 7]) * w;
            *(float4*)dst       = o0;
            *(float4*)(dst + 4) = o1;
        }
    }
}

// ---------------------------------------------------------------------------
// k_combine: y[t] = yslots[2t] + yslots[2t+1]
// ---------------------------------------------------------------------------
__global__ void k_combine(float* __restrict__ y)
{
    const int gi = blockIdx.x * blockDim.x + threadIdx.x;  // float4 index
    const int t  = gi >> 6;          // 64 float4 per row
    const int c4 = (gi & 63) << 2;
    const float4 a = *(const float4*)&g_yslots[((size_t)2 * t)     * OUTD + c4];
    const float4 b = *(const float4*)&g_yslots[((size_t)2 * t + 1) * OUTD + c4];
    float4 o;
    o.x = a.x + b.x; o.y = a.y + b.y; o.z = a.z + b.z; o.w = a.w + b.w;
    *(float4*)&y[(size_t)t * OUTD + c4] = o;
}

// ---------------------------------------------------------------------------
extern "C" void kernel_launch(void* const* d_in, const int* in_sizes, int n_in,
                              void* d_out, int out_size)
{
    const float* x    = (const float*)d_in[0];
    const float* bias = (const float*)d_in[1];
    const float* W1   = (const float*)d_in[2];
    const float* b1   = (const float*)d_in[3];
    const float* W2   = (const float*)d_in[4];
    const float* b2   = (const float*)d_in[5];
    const float* g1   = (const float*)d_in[6];
    const float* gb1  = (const float*)d_in[7];
    const float* g2   = (const float*)d_in[8];
    const float* gb2  = (const float*)d_in[9];
    const float* g3   = (const float*)d_in[10];
    const float* gb3  = (const float*)d_in[11];

    float* y_out = (float*)d_out;
    float* p_out = y_out + (size_t)BATCH * OUTD;

    float *Y1p = nullptr, *Y2p = nullptr;
    cudaGetSymbolAddress((void**)&Y1p, g_Y1);
    cudaGetSymbolAddress((void**)&Y2p, g_Y2);

    cudaFuncSetAttribute(k_expert, cudaFuncAttributeMaxDynamicSharedMemorySize,
                         EXPERT_SMEM);

    k_zero<<<1, 32>>>();

    // gate layer 1: [65536,256] @ [256,1024] -> relu
    k_gemm_bias_relu<<<dim3(GHID / 256, BATCH / 128), 512>>>(
        x, g1, gb1, Y1p, BATCH, GHID, DIM);

    // gate layer 2: [65536,1024] @ [1024,256] -> relu
    k_gemm_bias_relu<<<dim3(DIM / 256, BATCH / 128), 512>>>(
        Y1p, g2, gb2, Y2p, BATCH, DIM, GHID);

    // gate layer 3 + softmax + top-2 + p output
    k_gate3<<<BATCH / 8, 256>>>(Y2p, g3, gb3, p_out);

    k_scan<<<1, 1>>>();
    k_scatter<<<(BATCH * 2) / 256, 256>>>();

    // grouped expert GEMM (upper bound on tiles: 2B/128 + E = 1040)
    k_expert<<<1040, 512, EXPERT_SMEM>>>(x, bias, W1, b1, W2, b2);

    // y = slot0 + slot1
    k_combine<<<(BATCH * 64) / 256, 256>>>(y_out);
}

// round 7
// speedup vs baseline: 1.0002x; 1.0002x over previous
#include <cuda_runtime.h>
#include <math.h>
#include <stdint.h>

// ---------------------------------------------------------------------------
// MoELayer: B=65536 tokens, D=256, E=16 experts, H=256, O=256, TOP_K=2
// out = [ y (B*O floats) | p (B*E floats) ]
// ---------------------------------------------------------------------------

#define BATCH   65536
#define DIM     256
#define NEXP    16
#define HID     256
#define OUTD    256
#define GHID    1024   // 4*D

// ---------------- scratch (device globals; no allocations allowed) ----------
__device__ float    g_Y1[(size_t)BATCH * GHID];    // 256 MB gate hidden 1
__device__ float    g_Y2[(size_t)BATCH * DIM];     //  64 MB gate hidden 2
__device__ float    g_w[BATCH * 2];                // renormalized top-2 weights
__device__ int      g_eidx[BATCH * 2];             // top-2 expert ids
__device__ int      g_counts[NEXP];
__device__ int      g_offsets[NEXP + 1];
__device__ int      g_cursor[NEXP];
__device__ unsigned g_list[BATCH * 2];             // entry = token*2 + slot
__device__ float    g_yslots[(size_t)BATCH * 2 * OUTD];  // 128 MB per-slot out

// ---------------------------------------------------------------------------
// k_zero: reset histograms (graph replays need this every iteration)
// ---------------------------------------------------------------------------
__global__ void k_zero() {
    int i = threadIdx.x;
    if (i < NEXP) g_counts[i] = 0;
}

// ---------------------------------------------------------------------------
// Generic fp32 SIMT GEMM: C = relu(A[M,K] @ B[K,N] + bias[N])
// tile 128x256, BK=16, 512 threads, 8x8 per thread.
// Requires M%128==0, N%256==0, K%16==0 (true for all our shapes).
// ---------------------------------------------------------------------------
__global__ __launch_bounds__(512, 1)
void k_gemm_bias_relu(const float* __restrict__ A, const float* __restrict__ B,
                      const float* __restrict__ bv, float* __restrict__ C,
                      int M, int N, int K)
{
    __shared__ float As[16 * 128];
    __shared__ float Bs[16 * 256];

    const int tid = threadIdx.x;
    const int tx = tid & 31;        // n-group (0..31) -> 8 cols each
    const int ty = tid >> 5;        // m-group (0..15) -> 8 rows each
    const int m0 = blockIdx.y * 128;
    const int n0 = blockIdx.x * 256;

    const int a_r = tid >> 2;              // 0..127
    const int a_c = (tid & 3) << 2;        // 0,4,8,12
    const int b_r = tid >> 6;              // 0..7
    const int b_c = (tid & 63) << 2;       // 0..252

    const float* Arow = A + (size_t)(m0 + a_r) * K + a_c;
    const float* Bp   = B + (size_t)b_r * N + n0 + b_c;

    float acc[8][8];
#pragma unroll
    for (int i = 0; i < 8; i++)
#pragma unroll
        for (int j = 0; j < 8; j++) acc[i][j] = 0.f;

    for (int k0 = 0; k0 < K; k0 += 16) {
        float4 av = *(const float4*)(Arow + k0);
        As[(a_c + 0) * 128 + a_r] = av.x;
        As[(a_c + 1) * 128 + a_r] = av.y;
        As[(a_c + 2) * 128 + a_r] = av.z;
        As[(a_c + 3) * 128 + a_r] = av.w;
        *(float4*)&Bs[b_r * 256 + b_c]       = *(const float4*)(Bp + (size_t)k0 * N);
        *(float4*)&Bs[(b_r + 8) * 256 + b_c] = *(const float4*)(Bp + (size_t)(k0 + 8) * N);
        __syncthreads();

#pragma unroll
        for (int kk = 0; kk < 16; kk++) {
            float ar[8], br[8];
            *(float4*)&ar[0] = *(const float4*)&As[kk * 128 + ty * 8];
            *(float4*)&ar[4] = *(const float4*)&As[kk * 128 + ty * 8 + 4];
            *(float4*)&br[0] = *(const float4*)&Bs[kk * 256 + tx * 8];
            *(float4*)&br[4] = *(const float4*)&Bs[kk * 256 + tx * 8 + 4];
#pragma unroll
            for (int i = 0; i < 8; i++)
#pragma unroll
                for (int j = 0; j < 8; j++)
                    acc[i][j] = fmaf(ar[i], br[j], acc[i][j]);
        }
        __syncthreads();
    }

    // epilogue: + bias, relu, store
    float bb[8];
#pragma unroll
    for (int j = 0; j < 8; j++) bb[j] = bv[n0 + tx * 8 + j];
#pragma unroll
    for (int i = 0; i < 8; i++) {
        const int m = m0 + ty * 8 + i;
        float* crow = C + (size_t)m * N + n0 + tx * 8;
        float4 o0, o1;
        o0.x = fmaxf(acc[i][0] + bb[0], 0.f);
        o0.y = fmaxf(acc[i][1] + bb[1], 0.f);
        o0.z = fmaxf(acc[i][2] + bb[2], 0.f);
        o0.w = fmaxf(acc[i][3] + bb[3], 0.f);
        o1.x = fmaxf(acc[i][4] + bb[4], 0.f);
        o1.y = fmaxf(acc[i][5] + bb[5], 0.f);
        o1.z = fmaxf(acc[i][6] + bb[6], 0.f);
        o1.w = fmaxf(acc[i][7] + bb[7], 0.f);
        *(float4*)crow       = o0;
        *(float4*)(crow + 4) = o1;
    }
}

// ---------------------------------------------------------------------------
// k_gate3: one warp per token. logits = Y2 @ g3 + gb3; softmax(T=1);
// top-2 on logits (ties -> lowest index, matching lax.top_k); renormalize;
// write sparse p to output; record (e0,e1,w0,w1); histogram counts.
// grid = 8192 blocks x 256 threads = exactly 65536 warps.
// ---------------------------------------------------------------------------
__global__ void k_gate3(const float* __restrict__ Y2, const float* __restrict__ g3,
                        const float* __restrict__ gb3, float* __restrict__ p_out)
{
    __shared__ float sg3[NEXP * DIM];   // transposed: [e][k]
    __shared__ float sgb3[NEXP];
    for (int i = threadIdx.x; i < NEXP * DIM; i += blockDim.x) {
        int k = i >> 4, e = i & 15;
        sg3[e * DIM + k] = g3[i];
    }
    if (threadIdx.x < NEXP) sgb3[threadIdx.x] = gb3[threadIdx.x];
    __syncthreads();

    const int gw   = (blockIdx.x * blockDim.x + threadIdx.x) >> 5;  // token
    const int lane = threadIdx.x & 31;

    const float* y = Y2 + (size_t)gw * DIM;
    float yv[8];
#pragma unroll
    for (int i = 0; i < 8; i++) yv[i] = y[lane + 32 * i];

    float l[NEXP];
#pragma unroll
    for (int e = 0; e < NEXP; e++) {
        float s = 0.f;
#pragma unroll
        for (int i = 0; i < 8; i++)
            s = fmaf(yv[i], sg3[e * DIM + lane + 32 * i], s);
        l[e] = s;
    }
#pragma unroll
    for (int off = 16; off > 0; off >>= 1)
#pragma unroll
        for (int e = 0; e < NEXP; e++)
            l[e] += __shfl_xor_sync(0xffffffffu, l[e], off);
#pragma unroll
    for (int e = 0; e < NEXP; e++) l[e] += sgb3[e];

    // top-2 on logits (monotonic w.r.t. softmax probs)
    int i1 = 0; float t1 = l[0];
#pragma unroll
    for (int e = 1; e < NEXP; e++) if (l[e] > t1) { t1 = l[e]; i1 = e; }
    int i2 = -1; float t2 = -INFINITY;
#pragma unroll
    for (int e = 0; e < NEXP; e++) if (e != i1 && l[e] > t2) { t2 = l[e]; i2 = e; }

    // softmax values for the two selected experts
    const float mx = t1;
    float se = 0.f;
#pragma unroll
    for (int e = 0; e < NEXP; e++) se += expf(l[e] - mx);
    const float inv = 1.f / se;
    const float v1 = expf(t1 - mx) * inv;
    const float v2 = expf(t2 - mx) * inv;
    const float dn = 1.f / (v1 + v2 + 1e-9f);
    const float w0 = v1 * dn, w1 = v2 * dn;

    if (lane < NEXP) {
        float pv = (lane == i1) ? w0 : ((lane == i2) ? w1 : 0.f);
        p_out[(size_t)gw * NEXP + lane] = pv;
    }
    if (lane == 0) {
        g_w[gw * 2 + 0]    = w0;
        g_w[gw * 2 + 1]    = w1;
        g_eidx[gw * 2 + 0] = i1;
        g_eidx[gw * 2 + 1] = i2;
        atomicAdd(&g_counts[i1], 1);
        atomicAdd(&g_counts[i2], 1);
    }
}

// ---------------------------------------------------------------------------
// k_scan: serial exclusive scan of 16 counts; zero cursors.
// ---------------------------------------------------------------------------
__global__ void k_scan() {
    if (threadIdx.x == 0) {
        int acc = 0;
        for (int i = 0; i < NEXP; i++) {
            g_offsets[i] = acc;
            acc += g_counts[i];
            g_cursor[i] = 0;
        }
        g_offsets[NEXP] = acc;
    }
}

// ---------------------------------------------------------------------------
// k_scatter: bucket entries by expert.
// ---------------------------------------------------------------------------
__global__ void k_scatter() {
    int i = blockIdx.x * blockDim.x + threadIdx.x;   // entry = token*2 + slot
    if (i >= BATCH * 2) return;
    int e = g_eidx[i];
    int pos = atomicAdd(&g_cursor[e], 1);
    g_list[g_offsets[e] + pos] = (unsigned)i;
}

// ---------------------------------------------------------------------------
// k_expert: grouped expert GEMM. Each block = one 128-row tile of one expert.
//   stage 1: H[128,256] = relu((gather(x)+bias[e]) @ W1[e] + b1[e])  -> smem
//   stage 2: OUT[128,256] = (H @ W2[e] + b2[e]) * w  -> g_yslots rows
// dynamic smem: Hs(128x260) + As(16x128) + Bs(16x256) + bias rows + meta
// ---------------------------------------------------------------------------
#define HPAD 260
#define EXPERT_SMEM ((128*HPAD + 16*128 + 16*256 + 3*256 + 128) * 4 + 128 * 4)

__global__ __launch_bounds__(512, 1)
void k_expert(const float* __restrict__ x, const float* __restrict__ bias,
              const float* __restrict__ W1, const float* __restrict__ b1,
              const float* __restrict__ W2, const float* __restrict__ b2)
{
    extern __shared__ float sm[];
    float* Hs     = sm;                         // 128*HPAD
    float* As     = Hs + 128 * HPAD;            // 16*128
    float* Bs     = As + 16 * 128;              // 16*256
    float* s_bias = Bs + 16 * 256;              // 256
    float* s_b1   = s_bias + 256;               // 256
    float* s_b2   = s_b1 + 256;                 // 256
    float* s_w    = s_b2 + 256;                 // 128
    int*   s_ent  = (int*)(s_w + 128);          // 128
    __shared__ int s_meta[3];

    const int tid = threadIdx.x;

    if (tid == 0) {
        int bid = blockIdx.x, acc = 0, e = -1, row0 = 0, cnt = 0;
        for (int i = 0; i < NEXP; i++) {
            int c  = g_counts[i];
            int nt = (c + 127) >> 7;
            if (e < 0 && bid < acc + nt) {
                int tt = bid - acc;
                e = i;
                row0 = g_offsets[i] + tt * 128;
                cnt  = c - tt * 128;
                if (cnt > 128) cnt = 128;
            }
            acc += nt;
        }
        s_meta[0] = e; s_meta[1] = row0; s_meta[2] = cnt;
    }
    __syncthreads();

    const int e = s_meta[0];
    if (e < 0) return;
    const int row0 = s_meta[1];
    const int cnt  = s_meta[2];

    if (tid < 128) {
        unsigned ent = g_list[row0 + ((tid < cnt) ? tid : 0)];
        s_ent[tid] = (int)ent;
        s_w[tid]   = g_w[ent];
    }
    for (int i = tid; i < 256; i += 512) {
        s_bias[i] = bias[e * 256 + i];
        s_b1[i]   = b1[e * 256 + i];
        s_b2[i]   = b2[e * 256 + i];
    }
    __syncthreads();

    const int tx = tid & 31, ty = tid >> 5;
    const int a_r = tid >> 2, a_c = (tid & 3) << 2;
    const int b_r = tid >> 6, b_c = (tid & 63) << 2;

    const int tok = s_ent[a_r] >> 1;
    const float* xrow = x + (size_t)tok * DIM;

    float acc[8][8];
#pragma unroll
    for (int i = 0; i < 8; i++)
#pragma unroll
        for (int j = 0; j < 8; j++) acc[i][j] = 0.f;

    // ------------------ stage 1: H = relu((x+bias) @ W1 + b1) ---------------
    const float* W1e = W1 + (size_t)e * DIM * HID;
    for (int k0 = 0; k0 < DIM; k0 += 16) {
        float4 av = *(const float4*)(xrow + k0 + a_c);
        float4 bb = *(const float4*)(s_bias + k0 + a_c);
        As[(a_c + 0) * 128 + a_r] = av.x + bb.x;
        As[(a_c + 1) * 128 + a_r] = av.y + bb.y;
        As[(a_c + 2) * 128 + a_r] = av.z + bb.z;
        As[(a_c + 3) * 128 + a_r] = av.w + bb.w;
        *(float4*)&Bs[b_r * 256 + b_c]       = *(const float4*)(W1e + (size_t)(k0 + b_r) * HID + b_c);
        *(float4*)&Bs[(b_r + 8) * 256 + b_c] = *(const float4*)(W1e + (size_t)(k0 + b_r + 8) * HID + b_c);
        __syncthreads();
#pragma unroll
        for (int kk = 0; kk < 16; kk++) {
            float ar[8], br[8];
            *(float4*)&ar[0] = *(const float4*)&As[kk * 128 + ty * 8];
            *(float4*)&ar[4] = *(const float4*)&As[kk * 128 + ty * 8 + 4];
            *(float4*)&br[0] = *(const float4*)&Bs[kk * 256 + tx * 8];
            *(float4*)&br[4] = *(const float4*)&Bs[kk * 256 + tx * 8 + 4];
#pragma unroll
            for (int i = 0; i < 8; i++)
#pragma unroll
                for (int j = 0; j < 8; j++)
                    acc[i][j] = fmaf(ar[i], br[j], acc[i][j]);
        }
        __syncthreads();
    }
    // write H tile to smem (relu + b1)
#pragma unroll
    for (int i = 0; i < 8; i++) {
        const int m = ty * 8 + i;
        float4 h0, h1;
        h0.x = fmaxf(acc[i][0] + s_b1[tx * 8 + 0], 0.f);
        h0.y = fmaxf(acc[i][1] + s_b1[tx * 8 + 1], 0.f);
        h0.z = fmaxf(acc[i][2] + s_b1[tx * 8 + 2], 0.f);
        h0.w = fmaxf(acc[i][3] + s_b1[tx * 8 + 3], 0.f);
        h1.x = fmaxf(acc[i][4] + s_b1[tx * 8 + 4], 0.f);
        h1.y = fmaxf(acc[i][5] + s_b1[tx * 8 + 5], 0.f);
        h1.z = fmaxf(acc[i][6] + s_b1[tx * 8 + 6], 0.f);
        h1.w = fmaxf(acc[i][7] + s_b1[tx * 8 + 7], 0.f);
        *(float4*)&Hs[m * HPAD + tx * 8]     = h0;
        *(float4*)&Hs[m * HPAD + tx * 8 + 4] = h1;
    }
    __syncthreads();

    // ------------------ stage 2: OUT = (H @ W2 + b2) * w --------------------
#pragma unroll
    for (int i = 0; i < 8; i++)
#pragma unroll
        for (int j = 0; j < 8; j++) acc[i][j] = 0.f;

    const float* W2e = W2 + (size_t)e * HID * OUTD;
    for (int k0 = 0; k0 < HID; k0 += 16) {
        *(float4*)&Bs[b_r * 256 + b_c]       = *(const float4*)(W2e + (size_t)(k0 + b_r) * OUTD + b_c);
        *(float4*)&Bs[(b_r + 8) * 256 + b_c] = *(const float4*)(W2e + (size_t)(k0 + b_r + 8) * OUTD + b_c);
        __syncthreads();
#pragma unroll
        for (int kk = 0; kk < 16; kk++) {
            float ar[8], br[8];
#pragma unroll
            for (int i = 0; i < 8; i++)
                ar[i] = Hs[(ty * 8 + i) * HPAD + k0 + kk];   // warp-broadcast
            *(float4*)&br[0] = *(const float4*)&Bs[kk * 256 + tx * 8];
            *(float4*)&br[4] = *(const float4*)&Bs[kk * 256 + tx * 8 + 4];
#pragma unroll
            for (int i = 0; i < 8; i++)
#pragma unroll
                for (int j = 0; j < 8; j++)
                    acc[i][j] = fmaf(ar[i], br[j], acc[i][j]);
        }
        __syncthreads();
    }

#pragma unroll
    for (int i = 0; i < 8; i++) {
        const int m = ty * 8 + i;
        if (m < cnt) {
            const unsigned ent = (unsigned)s_ent[m];
            const float w = s_w[m];
            float* dst = g_yslots + (size_t)ent * OUTD + tx * 8;
            float4 o0, o1;
            o0.x = (acc[i][0] + s_b2[tx * 8 + 0]) * w;
            o0.y = (acc[i][1] + s_b2[tx * 8 + 1]) * w;
            o0.z = (acc[i][2] + s_b2[tx * 8 + 2]) * w;
            o0.w = (acc[i][3] + s_b2[tx * 8 + 3]) * w;
            o1.x = (acc[i][4] + s_b2[tx * 8 + 4]) * w;
            o1.y = (acc[i][5] + s_b2[tx * 8 + 5]) * w;
            o1.z = (acc[i][6] + s_b2[tx * 8 + 6]) * w;
            o1.w = (acc[i][7] + s_b2[tx * 8 + 7]) * w;
            *(float4*)dst       = o0;
            *(float4*)(dst + 4) = o1;
        }
    }
}

// ---------------------------------------------------------------------------
// k_combine: y[t] = yslots[2t] + yslots[2t+1]
// ---------------------------------------------------------------------------
__global__ void k_combine(float* __restrict__ y)
{
    const int gi = blockIdx.x * blockDim.x + threadIdx.x;  // float4 index
    const int t  = gi >> 6;          // 64 float4 per row
    const int c4 = (gi & 63) << 2;
    const float4 a = *(const float4*)&g_yslots[((size_t)2 * t)     * OUTD + c4];
    const float4 b = *(const float4*)&g_yslots[((size_t)2 * t + 1) * OUTD + c4];
    float4 o;
    o.x = a.x + b.x; o.y = a.y + b.y; o.z = a.z + b.z; o.w = a.w + b.w;
    *(float4*)&y[(size_t)t * OUTD + c4] = o;
}

// ---------------------------------------------------------------------------
extern "C" void kernel_launch(void* const* d_in, const int* in_sizes, int n_in,
                              void* d_out, int out_size)
{
    const float* x    = (const float*)d_in[0];
    const float* bias = (const float*)d_in[1];
    const float* W1   = (const float*)d_in[2];
    const float* b1   = (const float*)d_in[3];
    const float* W2   = (const float*)d_in[4];
    const float* b2   = (const float*)d_in[5];
    const float* g1   = (const float*)d_in[6];
    const float* gb1  = (const float*)d_in[7];
    const float* g2   = (const float*)d_in[8];
    const float* gb2  = (const float*)d_in[9];
    const float* g3   = (const float*)d_in[10];
    const float* gb3  = (const float*)d_in[11];

    float* y_out = (float*)d_out;
    float* p_out = y_out + (size_t)BATCH * OUTD;

    float *Y1p = nullptr, *Y2p = nullptr;
    cudaGetSymbolAddress((void**)&Y1p, g_Y1);
    cudaGetSymbolAddress((void**)&Y2p, g_Y2);

    cudaFuncSetAttribute(k_expert, cudaFuncAttributeMaxDynamicSharedMemorySize,
                         EXPERT_SMEM);

    k_zero<<<1, 32>>>();

    // gate layer 1: [65536,256] @ [256,1024] -> relu
    k_gemm_bias_relu<<<dim3(GHID / 256, BATCH / 128), 512>>>(
        x, g1, gb1, Y1p, BATCH, GHID, DIM);

    // gate layer 2: [65536,1024] @ [1024,256] -> relu
    k_gemm_bias_relu<<<dim3(DIM / 256, BATCH / 128), 512>>>(
        Y1p, g2, gb2, Y2p, BATCH, DIM, GHID);

    // gate layer 3 + softmax + top-2 + p output
    k_gate3<<<BATCH / 8, 256>>>(Y2p, g3, gb3, p_out);

    k_scan<<<1, 1>>>();
    k_scatter<<<(BATCH * 2) / 256, 256>>>();

    // grouped expert GEMM (upper bound on tiles: 2B/128 + E = 1040)
    k_expert<<<1040, 512, EXPERT_SMEM>>>(x, bias, W1, b1, W2, b2);

    // y = slot0 + slot1
    k_combine<<<(BATCH * 64) / 256, 256>>>(y_out);
}

// round 8
// speedup vs baseline: 1.0003x; 1.0002x over previous
#include <cuda_runtime.h>
#include <math.h>
#include <stdint.h>

// ---------------------------------------------------------------------------
// MoELayer: B=65536 tokens, D=256, E=16 experts, H=256, O=256, TOP_K=2
// out = [ y (B*O floats) | p (B*E floats) ]
// ---------------------------------------------------------------------------

#define BATCH   65536
#define DIM     256
#define NEXP    16
#define HID     256
#define OUTD    256
#define GHID    1024   // 4*D

// ---------------- scratch (device globals; no allocations allowed) ----------
__device__ float    g_Y1[(size_t)BATCH * GHID];    // 256 MB gate hidden 1
__device__ float    g_Y2[(size_t)BATCH * DIM];     //  64 MB gate hidden 2
__device__ float    g_w[BATCH * 2];                // renormalized top-2 weights
__device__ int      g_eidx[BATCH * 2];             // top-2 expert ids
__device__ int      g_counts[NEXP];
__device__ int      g_offsets[NEXP + 1];
__device__ int      g_cursor[NEXP];
__device__ unsigned g_list[BATCH * 2];             // entry = token*2 + slot
__device__ float    g_yslots[(size_t)BATCH * 2 * OUTD];  // 128 MB per-slot out

// ---------------------------------------------------------------------------
// k_zero: reset histograms (graph replays need this every iteration)
// ---------------------------------------------------------------------------
__global__ void k_zero() {
    int i = threadIdx.x;
    if (i < NEXP) g_counts[i] = 0;
}

// ---------------------------------------------------------------------------
// Generic fp32 SIMT GEMM: C = relu(A[M,K] @ B[K,N] + bias[N])
// tile 128x256, BK=16, 512 threads, 8x8 per thread.
// Requires M%128==0, N%256==0, K%16==0 (true for all our shapes).
// ---------------------------------------------------------------------------
__global__ __launch_bounds__(512, 1)
void k_gemm_bias_relu(const float* __restrict__ A, const float* __restrict__ B,
                      const float* __restrict__ bv, float* __restrict__ C,
                      int M, int N, int K)
{
    __shared__ float As[16 * 128];
    __shared__ float Bs[16 * 256];

    const int tid = threadIdx.x;
    const int tx = tid & 31;        // n-group (0..31) -> 8 cols each
    const int ty = tid >> 5;        // m-group (0..15) -> 8 rows each
    const int m0 = blockIdx.y * 128;
    const int n0 = blockIdx.x * 256;

    const int a_r = tid >> 2;              // 0..127
    const int a_c = (tid & 3) << 2;        // 0,4,8,12
    const int b_r = tid >> 6;              // 0..7
    const int b_c = (tid & 63) << 2;       // 0..252

    const float* Arow = A + (size_t)(m0 + a_r) * K + a_c;
    const float* Bp   = B + (size_t)b_r * N + n0 + b_c;

    float acc[8][8];
#pragma unroll
    for (int i = 0; i < 8; i++)
#pragma unroll
        for (int j = 0; j < 8; j++) acc[i][j] = 0.f;

    for (int k0 = 0; k0 < K; k0 += 16) {
        float4 av = *(const float4*)(Arow + k0);
        As[(a_c + 0) * 128 + a_r] = av.x;
        As[(a_c + 1) * 128 + a_r] = av.y;
        As[(a_c + 2) * 128 + a_r] = av.z;
        As[(a_c + 3) * 128 + a_r] = av.w;
        *(float4*)&Bs[b_r * 256 + b_c]       = *(const float4*)(Bp + (size_t)k0 * N);
        *(float4*)&Bs[(b_r + 8) * 256 + b_c] = *(const float4*)(Bp + (size_t)(k0 + 8) * N);
        __syncthreads();

#pragma unroll
        for (int kk = 0; kk < 16; kk++) {
            float ar[8], br[8];
            *(float4*)&ar[0] = *(const float4*)&As[kk * 128 + ty * 8];
            *(float4*)&ar[4] = *(const float4*)&As[kk * 128 + ty * 8 + 4];
            *(float4*)&br[0] = *(const float4*)&Bs[kk * 256 + tx * 8];
            *(float4*)&br[4] = *(const float4*)&Bs[kk * 256 + tx * 8 + 4];
#pragma unroll
            for (int i = 0; i < 8; i++)
#pragma unroll
                for (int j = 0; j < 8; j++)
                    acc[i][j] = fmaf(ar[i], br[j], acc[i][j]);
        }
        __syncthreads();
    }

    // epilogue: + bias, relu, store
    float bb[8];
#pragma unroll
    for (int j = 0; j < 8; j++) bb[j] = bv[n0 + tx * 8 + j];
#pragma unroll
    for (int i = 0; i < 8; i++) {
        const int m = m0 + ty * 8 + i;
        float* crow = C + (size_t)m * N + n0 + tx * 8;
        float4 o0, o1;
        o0.x = fmaxf(acc[i][0] + bb[0], 0.f);
        o0.y = fmaxf(acc[i][1] + bb[1], 0.f);
        o0.z = fmaxf(acc[i][2] + bb[2], 0.f);
        o0.w = fmaxf(acc[i][3] + bb[3], 0.f);
        o1.x = fmaxf(acc[i][4] + bb[4], 0.f);
        o1.y = fmaxf(acc[i][5] + bb[5], 0.f);
        o1.z = fmaxf(acc[i][6] + bb[6], 0.f);
        o1.w = fmaxf(acc[i][7] + bb[7], 0.f);
        *(float4*)crow       = o0;
        *(float4*)(crow + 4) = o1;
    }
}

// ---------------------------------------------------------------------------
// k_gate3: one warp per token. logits = Y2 @ g3 + gb3; softmax(T=1);
// top-2 on logits (ties -> lowest index, matching lax.top_k); renormalize;
// write sparse p to output; record (e0,e1,w0,w1); histogram counts.
// grid = 8192 blocks x 256 threads = exactly 65536 warps.
// ---------------------------------------------------------------------------
__global__ void k_gate3(const float* __restrict__ Y2, const float* __restrict__ g3,
                        const float* __restrict__ gb3, float* __restrict__ p_out)
{
    __shared__ float sg3[NEXP * DIM];   // transposed: [e][k]
    __shared__ float sgb3[NEXP];
    for (int i = threadIdx.x; i < NEXP * DIM; i += blockDim.x) {
        int k = i >> 4, e = i & 15;
        sg3[e * DIM + k] = g3[i];
    }
    if (threadIdx.x < NEXP) sgb3[threadIdx.x] = gb3[threadIdx.x];
    __syncthreads();

    const int gw   = (blockIdx.x * blockDim.x + threadIdx.x) >> 5;  // token
    const int lane = threadIdx.x & 31;

    const float* y = Y2 + (size_t)gw * DIM;
    float yv[8];
#pragma unroll
    for (int i = 0; i < 8; i++) yv[i] = y[lane + 32 * i];

    float l[NEXP];
#pragma unroll
    for (int e = 0; e < NEXP; e++) {
        float s = 0.f;
#pragma unroll
        for (int i = 0; i < 8; i++)
            s = fmaf(yv[i], sg3[e * DIM + lane + 32 * i], s);
        l[e] = s;
    }
#pragma unroll
    for (int off = 16; off > 0; off >>= 1)
#pragma unroll
        for (int e = 0; e < NEXP; e++)
            l[e] += __shfl_xor_sync(0xffffffffu, l[e], off);
#pragma unroll
    for (int e = 0; e < NEXP; e++) l[e] += sgb3[e];

    // top-2 on logits (monotonic w.r.t. softmax probs)
    int i1 = 0; float t1 = l[0];
#pragma unroll
    for (int e = 1; e < NEXP; e++) if (l[e] > t1) { t1 = l[e]; i1 = e; }
    int i2 = -1; float t2 = -INFINITY;
#pragma unroll
    for (int e = 0; e < NEXP; e++) if (e != i1 && l[e] > t2) { t2 = l[e]; i2 = e; }

    // softmax values for the two selected experts
    const float mx = t1;
    float se = 0.f;
#pragma unroll
    for (int e = 0; e < NEXP; e++) se += expf(l[e] - mx);
    const float inv = 1.f / se;
    const float v1 = expf(t1 - mx) * inv;
    const float v2 = expf(t2 - mx) * inv;
    const float dn = 1.f / (v1 + v2 + 1e-9f);
    const float w0 = v1 * dn, w1 = v2 * dn;

    if (lane < NEXP) {
        float pv = (lane == i1) ? w0 : ((lane == i2) ? w1 : 0.f);
        p_out[(size_t)gw * NEXP + lane] = pv;
    }
    if (lane == 0) {
        g_w[gw * 2 + 0]    = w0;
        g_w[gw * 2 + 1]    = w1;
        g_eidx[gw * 2 + 0] = i1;
        g_eidx[gw * 2 + 1] = i2;
        atomicAdd(&g_counts[i1], 1);
        atomicAdd(&g_counts[i2], 1);
    }
}

// ---------------------------------------------------------------------------
// k_scan: serial exclusive scan of 16 counts; zero cursors.
// ---------------------------------------------------------------------------
__global__ void k_scan() {
    if (threadIdx.x == 0) {
        int acc = 0;
        for (int i = 0; i < NEXP; i++) {
            g_offsets[i] = acc;
            acc += g_counts[i];
            g_cursor[i] = 0;
        }
        g_offsets[NEXP] = acc;
    }
}

// ---------------------------------------------------------------------------
// k_scatter: bucket entries by expert.
// ---------------------------------------------------------------------------
__global__ void k_scatter() {
    int i = blockIdx.x * blockDim.x + threadIdx.x;   // entry = token*2 + slot
    if (i >= BATCH * 2) return;
    int e = g_eidx[i];
    int pos = atomicAdd(&g_cursor[e], 1);
    g_list[g_offsets[e] + pos] = (unsigned)i;
}

// ---------------------------------------------------------------------------
// k_expert: grouped expert GEMM. Each block = one 128-row tile of one expert.
//   stage 1: H[128,256] = relu((gather(x)+bias[e]) @ W1[e] + b1[e])  -> smem
//   stage 2: OUT[128,256] = (H @ W2[e] + b2[e]) * w  -> g_yslots rows
// dynamic smem: Hs(128x260) + As(16x128) + Bs(16x256) + bias rows + meta
// ---------------------------------------------------------------------------
#define HPAD 260
#define EXPERT_SMEM ((128*HPAD + 16*128 + 16*256 + 3*256 + 128) * 4 + 128 * 4)

__global__ __launch_bounds__(512, 1)
void k_expert(const float* __restrict__ x, const float* __restrict__ bias,
              const float* __restrict__ W1, const float* __restrict__ b1,
              const float* __restrict__ W2, const float* __restrict__ b2)
{
    extern __shared__ float sm[];
    float* Hs     = sm;                         // 128*HPAD
    float* As     = Hs + 128 * HPAD;            // 16*128
    float* Bs     = As + 16 * 128;              // 16*256
    float* s_bias = Bs + 16 * 256;              // 256
    float* s_b1   = s_bias + 256;               // 256
    float* s_b2   = s_b1 + 256;                 // 256
    float* s_w    = s_b2 + 256;                 // 128
    int*   s_ent  = (int*)(s_w + 128);          // 128
    __shared__ int s_meta[3];

    const int tid = threadIdx.x;

    if (tid == 0) {
        int bid = blockIdx.x, acc = 0, e = -1, row0 = 0, cnt = 0;
        for (int i = 0; i < NEXP; i++) {
            int c  = g_counts[i];
            int nt = (c + 127) >> 7;
            if (e < 0 && bid < acc + nt) {
                int tt = bid - acc;
                e = i;
                row0 = g_offsets[i] + tt * 128;
                cnt  = c - tt * 128;
                if (cnt > 128) cnt = 128;
            }
            acc += nt;
        }
        s_meta[0] = e; s_meta[1] = row0; s_meta[2] = cnt;
    }
    __syncthreads();

    const int e = s_meta[0];
    if (e < 0) return;
    const int row0 = s_meta[1];
    const int cnt  = s_meta[2];

    if (tid < 128) {
        unsigned ent = g_list[row0 + ((tid < cnt) ? tid : 0)];
        s_ent[tid] = (int)ent;
        s_w[tid]   = g_w[ent];
    }
    for (int i = tid; i < 256; i += 512) {
        s_bias[i] = bias[e * 256 + i];
        s_b1[i]   = b1[e * 256 + i];
        s_b2[i]   = b2[e * 256 + i];
    }
    __syncthreads();

    const int tx = tid & 31, ty = tid >> 5;
    const int a_r = tid >> 2, a_c = (tid & 3) << 2;
    const int b_r = tid >> 6, b_c = (tid & 63) << 2;

    const int tok = s_ent[a_r] >> 1;
    const float* xrow = x + (size_t)tok * DIM;

    float acc[8][8];
#pragma unroll
    for (int i = 0; i < 8; i++)
#pragma unroll
        for (int j = 0; j < 8; j++) acc[i][j] = 0.f;

    // ------------------ stage 1: H = relu((x+bias) @ W1 + b1) ---------------
    const float* W1e = W1 + (size_t)e * DIM * HID;
    for (int k0 = 0; k0 < DIM; k0 += 16) {
        float4 av = *(const float4*)(xrow + k0 + a_c);
        float4 bb = *(const float4*)(s_bias + k0 + a_c);
        As[(a_c + 0) * 128 + a_r] = av.x + bb.x;
        As[(a_c + 1) * 128 + a_r] = av.y + bb.y;
        As[(a_c + 2) * 128 + a_r] = av.z + bb.z;
        As[(a_c + 3) * 128 + a_r] = av.w + bb.w;
        *(float4*)&Bs[b_r * 256 + b_c]       = *(const float4*)(W1e + (size_t)(k0 + b_r) * HID + b_c);
        *(float4*)&Bs[(b_r + 8) * 256 + b_c] = *(const float4*)(W1e + (size_t)(k0 + b_r + 8) * HID + b_c);
        __syncthreads();
#pragma unroll
        for (int kk = 0; kk < 16; kk++) {
            float ar[8], br[8];
            *(float4*)&ar[0] = *(const float4*)&As[kk * 128 + ty * 8];
            *(float4*)&ar[4] = *(const float4*)&As[kk * 128 + ty * 8 + 4];
            *(float4*)&br[0] = *(const float4*)&Bs[kk * 256 + tx * 8];
            *(float4*)&br[4] = *(const float4*)&Bs[kk * 256 + tx * 8 + 4];
#pragma unroll
            for (int i = 0; i < 8; i++)
#pragma unroll
                for (int j = 0; j < 8; j++)
                    acc[i][j] = fmaf(ar[i], br[j], acc[i][j]);
        }
        __syncthreads();
    }
    // write H tile to smem (relu + b1)
#pragma unroll
    for (int i = 0; i < 8; i++) {
        const int m = ty * 8 + i;
        float4 h0, h1;
        h0.x = fmaxf(acc[i][0] + s_b1[tx * 8 + 0], 0.f);
        h0.y = fmaxf(acc[i][1] + s_b1[tx * 8 + 1], 0.f);
        h0.z = fmaxf(acc[i][2] + s_b1[tx * 8 + 2], 0.f);
        h0.w = fmaxf(acc[i][3] + s_b1[tx * 8 + 3], 0.f);
        h1.x = fmaxf(acc[i][4] + s_b1[tx * 8 + 4], 0.f);
        h1.y = fmaxf(acc[i][5] + s_b1[tx * 8 + 5], 0.f);
        h1.z = fmaxf(acc[i][6] + s_b1[tx * 8 + 6], 0.f);
        h1.w = fmaxf(acc[i][7] + s_b1[tx * 8 + 7], 0.f);
        *(float4*)&Hs[m * HPAD + tx * 8]     = h0;
        *(float4*)&Hs[m * HPAD + tx * 8 + 4] = h1;
    }
    __syncthreads();

    // ------------------ stage 2: OUT = (H @ W2 + b2) * w --------------------
#pragma unroll
    for (int i = 0; i < 8; i++)
#pragma unroll
        for (int j = 0; j < 8; j++) acc[i][j] = 0.f;

    const float* W2e = W2 + (size_t)e * HID * OUTD;
    for (int k0 = 0; k0 < HID; k0 += 16) {
        *(float4*)&Bs[b_r * 256 + b_c]       = *(const float4*)(W2e + (size_t)(k0 + b_r) * OUTD + b_c);
        *(float4*)&Bs[(b_r + 8) * 256 + b_c] = *(const float4*)(W2e + (size_t)(k0 + b_r + 8) * OUTD + b_c);
        __syncthreads();
#pragma unroll
        for (int kk = 0; kk < 16; kk++) {
            float ar[8], br[8];
#pragma unroll
            for (int i = 0; i < 8; i++)
                ar[i] = Hs[(ty * 8 + i) * HPAD + k0 + kk];   // warp-broadcast
            *(float4*)&br[0] = *(const float4*)&Bs[kk * 256 + tx * 8];
            *(float4*)&br[4] = *(const float4*)&Bs[kk * 256 + tx * 8 + 4];
#pragma unroll
            for (int i = 0; i < 8; i++)
#pragma unroll
                for (int j = 0; j < 8; j++)
                    acc[i][j] = fmaf(ar[i], br[j], acc[i][j]);
        }
        __syncthreads();
    }

#pragma unroll
    for (int i = 0; i < 8; i++) {
        const int m = ty * 8 + i;
        if (m < cnt) {
            const unsigned ent = (unsigned)s_ent[m];
            const float w = s_w[m];
            float* dst = g_yslots + (size_t)ent * OUTD + tx * 8;
            float4 o0, o1;
            o0.x = (acc[i][0] + s_b2[tx * 8 + 0]) * w;
            o0.y = (acc[i][1] + s_b2[tx * 8 + 1]) * w;
            o0.z = (acc[i][2] + s_b2[tx * 8 + 2]) * w;
            o0.w = (acc[i][3] + s_b2[tx * 8 + 3]) * w;
            o1.x = (acc[i][4] + s_b2[tx * 8 + 4]) * w;
            o1.y = (acc[i][5] + s_b2[tx * 8 + 5]) * w;
            o1.z = (acc[i][6] + s_b2[tx * 8 + 6]) * w;
            o1.w = (acc[i][7] + s_b2[tx * 8 + 7]) * w;
            *(float4*)dst       = o0;
            *(float4*)(dst + 4) = o1;
        }
    }
}

// ---------------------------------------------------------------------------
// k_combine: y[t] = yslots[2t] + yslots[2t+1]
// ---------------------------------------------------------------------------
__global__ void k_combine(float* __restrict__ y)
{
    const int gi = blockIdx.x * blockDim.x + threadIdx.x;  // float4 index
    const int t  = gi >> 6;          // 64 float4 per row
    const int c4 = (gi & 63) << 2;
    const float4 a = *(const float4*)&g_yslots[((size_t)2 * t)     * OUTD + c4];
    const float4 b = *(const float4*)&g_yslots[((size_t)2 * t + 1) * OUTD + c4];
    float4 o;
    o.x = a.x + b.x; o.y = a.y + b.y; o.z = a.z + b.z; o.w = a.w + b.w;
    *(float4*)&y[(size_t)t * OUTD + c4] = o;
}

// ---------------------------------------------------------------------------
extern "C" void kernel_launch(void* const* d_in, const int* in_sizes, int n_in,
                              void* d_out, int out_size)
{
    const float* x    = (const float*)d_in[0];
    const float* bias = (const float*)d_in[1];
    const float* W1   = (const float*)d_in[2];
    const float* b1   = (const float*)d_in[3];
    const float* W2   = (const float*)d_in[4];
    const float* b2   = (const float*)d_in[5];
    const float* g1   = (const float*)d_in[6];
    const float* gb1  = (const float*)d_in[7];
    const float* g2   = (const float*)d_in[8];
    const float* gb2  = (const float*)d_in[9];
    const float* g3   = (const float*)d_in[10];
    const float* gb3  = (const float*)d_in[11];

    float* y_out = (float*)d_out;
    float* p_out = y_out + (size_t)BATCH * OUTD;

    float *Y1p = nullptr, *Y2p = nullptr;
    cudaGetSymbolAddress((void**)&Y1p, g_Y1);
    cudaGetSymbolAddress((void**)&Y2p, g_Y2);

    cudaFuncSetAttribute(k_expert, cudaFuncAttributeMaxDynamicSharedMemorySize,
                         EXPERT_SMEM);

    k_zero<<<1, 32>>>();

    // gate layer 1: [65536,256] @ [256,1024] -> relu
    k_gemm_bias_relu<<<dim3(GHID / 256, BATCH / 128), 512>>>(
        x, g1, gb1, Y1p, BATCH, GHID, DIM);

    // gate layer 2: [65536,1024] @ [1024,256] -> relu
    k_gemm_bias_relu<<<dim3(DIM / 256, BATCH / 128), 512>>>(
        Y1p, g2, gb2, Y2p, BATCH, DIM, GHID);

    // gate layer 3 + softmax + top-2 + p output
    k_gate3<<<BATCH / 8, 256>>>(Y2p, g3, gb3, p_out);

    k_scan<<<1, 1>>>();
    k_scatter<<<(BATCH * 2) / 256, 256>>>();

    // grouped expert GEMM (upper bound on tiles: 2B/128 + E = 1040)
    k_expert<<<1040, 512, EXPERT_SMEM>>>(x, bias, W1, b1, W2, b2);

    // y = slot0 + slot1
    k_combine<<<(BATCH * 64) / 256, 256>>>(y_out);
}

// round 9
// speedup vs baseline: 1.0082x; 1.0079x over previous
#include <cuda_runtime.h>
#include <math.h>
#include <stdint.h>

// ---------------------------------------------------------------------------
// MoELayer: B=65536 tokens, D=256, E=16 experts, H=256, O=256, TOP_K=2
// out = [ y (B*O floats) | p (B*E floats) ]
// R8: all GEMM inner loops use packed fma.rn.f32x2 (FFMA2) -> 2x fp32 FMA rate
// ---------------------------------------------------------------------------

#define BATCH   65536
#define DIM     256
#define NEXP    16
#define HID     256
#define OUTD    256
#define GHID    1024   // 4*D

typedef unsigned long long u64;

// ---------------- packed f32x2 helpers (sm_103a) -----------------------------
__device__ __forceinline__ u64 bcast2(float x) {
    u64 r; asm("mov.b64 %0, {%1, %1};" : "=l"(r) : "f"(x)); return r;
}
__device__ __forceinline__ void ffma2(u64& d, u64 a, u64 b) {
    asm("fma.rn.f32x2 %0, %1, %2, %0;" : "+l"(d) : "l"(a), "l"(b));
}
__device__ __forceinline__ float2 unpack2(u64 v) {
    float2 f; asm("mov.b64 {%0, %1}, %2;" : "=f"(f.x), "=f"(f.y) : "l"(v)); return f;
}

// ---------------- scratch (device globals; no allocations allowed) ----------
__device__ float    g_Y1[(size_t)BATCH * GHID];    // 256 MB gate hidden 1
__device__ float    g_Y2[(size_t)BATCH * DIM];     //  64 MB gate hidden 2
__device__ float    g_w[BATCH * 2];                // renormalized top-2 weights
__device__ int      g_eidx[BATCH * 2];             // top-2 expert ids
__device__ int      g_counts[NEXP];
__device__ int      g_offsets[NEXP + 1];
__device__ int      g_cursor[NEXP];
__device__ unsigned g_list[BATCH * 2];             // entry = token*2 + slot
__device__ float    g_yslots[(size_t)BATCH * 2 * OUTD];  // 128 MB per-slot out

// ---------------------------------------------------------------------------
__global__ void k_zero() {
    int i = threadIdx.x;
    if (i < NEXP) g_counts[i] = 0;
}

// ---------------------------------------------------------------------------
// Generic fp32 GEMM via FFMA2: C = relu(A[M,K] @ B[K,N] + bias[N])
// tile 128x256, BK=16, 512 threads, 8x8 per thread (accs packed 8x4 f32x2).
// ---------------------------------------------------------------------------
__global__ __launch_bounds__(512, 1)
void k_gemm_bias_relu(const float* __restrict__ A, const float* __restrict__ B,
                      const float* __restrict__ bv, float* __restrict__ C,
                      int M, int N, int K)
{
    __shared__ float As[16 * 128];
    __shared__ float Bs[16 * 256];

    const int tid = threadIdx.x;
    const int tx = tid & 31;        // n-group (0..31) -> 8 cols each
    const int ty = tid >> 5;        // m-group (0..15) -> 8 rows each
    const int m0 = blockIdx.y * 128;
    const int n0 = blockIdx.x * 256;

    const int a_r = tid >> 2;              // 0..127
    const int a_c = (tid & 3) << 2;        // 0,4,8,12
    const int b_r = tid >> 6;              // 0..7
    const int b_c = (tid & 63) << 2;       // 0..252

    const float* Arow = A + (size_t)(m0 + a_r) * K + a_c;
    const float* Bp   = B + (size_t)b_r * N + n0 + b_c;

    u64 acc[8][4];
#pragma unroll
    for (int i = 0; i < 8; i++)
#pragma unroll
        for (int j = 0; j < 4; j++) acc[i][j] = 0ull;

    for (int k0 = 0; k0 < K; k0 += 16) {
        float4 av = *(const float4*)(Arow + k0);
        As[(a_c + 0) * 128 + a_r] = av.x;
        As[(a_c + 1) * 128 + a_r] = av.y;
        As[(a_c + 2) * 128 + a_r] = av.z;
        As[(a_c + 3) * 128 + a_r] = av.w;
        *(float4*)&Bs[b_r * 256 + b_c]       = *(const float4*)(Bp + (size_t)k0 * N);
        *(float4*)&Bs[(b_r + 8) * 256 + b_c] = *(const float4*)(Bp + (size_t)(k0 + 8) * N);
        __syncthreads();

#pragma unroll
        for (int kk = 0; kk < 16; kk++) {
            float ar[8];
            *(float4*)&ar[0] = *(const float4*)&As[kk * 128 + ty * 8];
            *(float4*)&ar[4] = *(const float4*)&As[kk * 128 + ty * 8 + 4];
            u64 ar2[8];
#pragma unroll
            for (int i = 0; i < 8; i++) ar2[i] = bcast2(ar[i]);
            const u64* bp64 = (const u64*)&Bs[kk * 256 + tx * 8];
            u64 br2[4];
            br2[0] = bp64[0]; br2[1] = bp64[1]; br2[2] = bp64[2]; br2[3] = bp64[3];
#pragma unroll
            for (int i = 0; i < 8; i++)
#pragma unroll
                for (int j = 0; j < 4; j++)
                    ffma2(acc[i][j], ar2[i], br2[j]);
        }
        __syncthreads();
    }

    // epilogue: + bias, relu, store
    float bb[8];
#pragma unroll
    for (int j = 0; j < 8; j++) bb[j] = bv[n0 + tx * 8 + j];
#pragma unroll
    for (int i = 0; i < 8; i++) {
        const int m = m0 + ty * 8 + i;
        float* crow = C + (size_t)m * N + n0 + tx * 8;
        float o[8];
#pragma unroll
        for (int j = 0; j < 4; j++) {
            float2 v = unpack2(acc[i][j]);
            o[2 * j]     = fmaxf(v.x + bb[2 * j], 0.f);
            o[2 * j + 1] = fmaxf(v.y + bb[2 * j + 1], 0.f);
        }
        *(float4*)crow       = *(float4*)&o[0];
        *(float4*)(crow + 4) = *(float4*)&o[4];
    }
}

// ---------------------------------------------------------------------------
// k_gate3: one warp per token. logits = Y2 @ g3 + gb3; softmax(T=1);
// top-2 on logits; renormalize; sparse p to output; histogram counts.
// ---------------------------------------------------------------------------
__global__ void k_gate3(const float* __restrict__ Y2, const float* __restrict__ g3,
                        const float* __restrict__ gb3, float* __restrict__ p_out)
{
    __shared__ float sg3[NEXP * DIM];   // transposed: [e][k]
    __shared__ float sgb3[NEXP];
    for (int i = threadIdx.x; i < NEXP * DIM; i += blockDim.x) {
        int k = i >> 4, e = i & 15;
        sg3[e * DIM + k] = g3[i];
    }
    if (threadIdx.x < NEXP) sgb3[threadIdx.x] = gb3[threadIdx.x];
    __syncthreads();

    const int gw   = (blockIdx.x * blockDim.x + threadIdx.x) >> 5;  // token
    const int lane = threadIdx.x & 31;

    const float* y = Y2 + (size_t)gw * DIM;
    float yv[8];
#pragma unroll
    for (int i = 0; i < 8; i++) yv[i] = y[lane + 32 * i];

    float l[NEXP];
#pragma unroll
    for (int e = 0; e < NEXP; e++) {
        float s = 0.f;
#pragma unroll
        for (int i = 0; i < 8; i++)
            s = fmaf(yv[i], sg3[e * DIM + lane + 32 * i], s);
        l[e] = s;
    }
#pragma unroll
    for (int off = 16; off > 0; off >>= 1)
#pragma unroll
        for (int e = 0; e < NEXP; e++)
            l[e] += __shfl_xor_sync(0xffffffffu, l[e], off);
#pragma unroll
    for (int e = 0; e < NEXP; e++) l[e] += sgb3[e];

    int i1 = 0; float t1 = l[0];
#pragma unroll
    for (int e = 1; e < NEXP; e++) if (l[e] > t1) { t1 = l[e]; i1 = e; }
    int i2 = -1; float t2 = -INFINITY;
#pragma unroll
    for (int e = 0; e < NEXP; e++) if (e != i1 && l[e] > t2) { t2 = l[e]; i2 = e; }

    const float mx = t1;
    float se = 0.f;
#pragma unroll
    for (int e = 0; e < NEXP; e++) se += expf(l[e] - mx);
    const float inv = 1.f / se;
    const float v1 = expf(t1 - mx) * inv;
    const float v2 = expf(t2 - mx) * inv;
    const float dn = 1.f / (v1 + v2 + 1e-9f);
    const float w0 = v1 * dn, w1 = v2 * dn;

    if (lane < NEXP) {
        float pv = (lane == i1) ? w0 : ((lane == i2) ? w1 : 0.f);
        p_out[(size_t)gw * NEXP + lane] = pv;
    }
    if (lane == 0) {
        g_w[gw * 2 + 0]    = w0;
        g_w[gw * 2 + 1]    = w1;
        g_eidx[gw * 2 + 0] = i1;
        g_eidx[gw * 2 + 1] = i2;
        atomicAdd(&g_counts[i1], 1);
        atomicAdd(&g_counts[i2], 1);
    }
}

// ---------------------------------------------------------------------------
__global__ void k_scan() {
    if (threadIdx.x == 0) {
        int acc = 0;
        for (int i = 0; i < NEXP; i++) {
            g_offsets[i] = acc;
            acc += g_counts[i];
            g_cursor[i] = 0;
        }
        g_offsets[NEXP] = acc;
    }
}

__global__ void k_scatter() {
    int i = blockIdx.x * blockDim.x + threadIdx.x;   // entry = token*2 + slot
    if (i >= BATCH * 2) return;
    int e = g_eidx[i];
    int pos = atomicAdd(&g_cursor[e], 1);
    g_list[g_offsets[e] + pos] = (unsigned)i;
}

// ---------------------------------------------------------------------------
// k_expert: grouped expert GEMM (FFMA2). Each block = 128-row tile of one expert.
//   stage 1: H[128,256] = relu((gather(x)+bias[e]) @ W1[e] + b1[e])  -> smem
//   stage 2: OUT[128,256] = (H @ W2[e] + b2[e]) * w  -> g_yslots rows
// ---------------------------------------------------------------------------
#define HPAD 260
#define EXPERT_SMEM ((128*HPAD + 16*128 + 16*256 + 3*256 + 128) * 4 + 128 * 4)

__global__ __launch_bounds__(512, 1)
void k_expert(const float* __restrict__ x, const float* __restrict__ bias,
              const float* __restrict__ W1, const float* __restrict__ b1,
              const float* __restrict__ W2, const float* __restrict__ b2)
{
    extern __shared__ float sm[];
    float* Hs     = sm;                         // 128*HPAD
    float* As     = Hs + 128 * HPAD;            // 16*128
    float* Bs     = As + 16 * 128;              // 16*256
    float* s_bias = Bs + 16 * 256;              // 256
    float* s_b1   = s_bias + 256;               // 256
    float* s_b2   = s_b1 + 256;                 // 256
    float* s_w    = s_b2 + 256;                 // 128
    int*   s_ent  = (int*)(s_w + 128);          // 128
    __shared__ int s_meta[3];

    const int tid = threadIdx.x;

    if (tid == 0) {
        int bid = blockIdx.x, acc = 0, e = -1, row0 = 0, cnt = 0;
        for (int i = 0; i < NEXP; i++) {
            int c  = g_counts[i];
            int nt = (c + 127) >> 7;
            if (e < 0 && bid < acc + nt) {
                int tt = bid - acc;
                e = i;
                row0 = g_offsets[i] + tt * 128;
                cnt  = c - tt * 128;
                if (cnt > 128) cnt = 128;
            }
            acc += nt;
        }
        s_meta[0] = e; s_meta[1] = row0; s_meta[2] = cnt;
    }
    __syncthreads();

    const int e = s_meta[0];
    if (e < 0) return;
    const int row0 = s_meta[1];
    const int cnt  = s_meta[2];

    if (tid < 128) {
        unsigned ent = g_list[row0 + ((tid < cnt) ? tid : 0)];
        s_ent[tid] = (int)ent;
        s_w[tid]   = g_w[ent];
    }
    for (int i = tid; i < 256; i += 512) {
        s_bias[i] = bias[e * 256 + i];
        s_b1[i]   = b1[e * 256 + i];
        s_b2[i]   = b2[e * 256 + i];
    }
    __syncthreads();

    const int tx = tid & 31, ty = tid >> 5;
    const int a_r = tid >> 2, a_c = (tid & 3) << 2;
    const int b_r = tid >> 6, b_c = (tid & 63) << 2;

    const int tok = s_ent[a_r] >> 1;
    const float* xrow = x + (size_t)tok * DIM;

    u64 acc[8][4];
#pragma unroll
    for (int i = 0; i < 8; i++)
#pragma unroll
        for (int j = 0; j < 4; j++) acc[i][j] = 0ull;

    // ------------------ stage 1: H = relu((x+bias) @ W1 + b1) ---------------
    const float* W1e = W1 + (size_t)e * DIM * HID;
    for (int k0 = 0; k0 < DIM; k0 += 16) {
        float4 av = *(const float4*)(xrow + k0 + a_c);
        float4 bb = *(const float4*)(s_bias + k0 + a_c);
        As[(a_c + 0) * 128 + a_r] = av.x + bb.x;
        As[(a_c + 1) * 128 + a_r] = av.y + bb.y;
        As[(a_c + 2) * 128 + a_r] = av.z + bb.z;
        As[(a_c + 3) * 128 + a_r] = av.w + bb.w;
        *(float4*)&Bs[b_r * 256 + b_c]       = *(const float4*)(W1e + (size_t)(k0 + b_r) * HID + b_c);
        *(float4*)&Bs[(b_r + 8) * 256 + b_c] = *(const float4*)(W1e + (size_t)(k0 + b_r + 8) * HID + b_c);
        __syncthreads();
#pragma unroll
        for (int kk = 0; kk < 16; kk++) {
            float ar[8];
            *(float4*)&ar[0] = *(const float4*)&As[kk * 128 + ty * 8];
            *(float4*)&ar[4] = *(const float4*)&As[kk * 128 + ty * 8 + 4];
            u64 ar2[8];
#pragma unroll
            for (int i = 0; i < 8; i++) ar2[i] = bcast2(ar[i]);
            const u64* bp64 = (const u64*)&Bs[kk * 256 + tx * 8];
            u64 br2[4];
            br2[0] = bp64[0]; br2[1] = bp64[1]; br2[2] = bp64[2]; br2[3] = bp64[3];
#pragma unroll
            for (int i = 0; i < 8; i++)
#pragma unroll
                for (int j = 0; j < 4; j++)
                    ffma2(acc[i][j], ar2[i], br2[j]);
        }
        __syncthreads();
    }
    // write H tile to smem (relu + b1)
#pragma unroll
    for (int i = 0; i < 8; i++) {
        const int m = ty * 8 + i;
        float o[8];
#pragma unroll
        for (int j = 0; j < 4; j++) {
            float2 v = unpack2(acc[i][j]);
            o[2 * j]     = fmaxf(v.x + s_b1[tx * 8 + 2 * j], 0.f);
            o[2 * j + 1] = fmaxf(v.y + s_b1[tx * 8 + 2 * j + 1], 0.f);
        }
        *(float4*)&Hs[m * HPAD + tx * 8]     = *(float4*)&o[0];
        *(float4*)&Hs[m * HPAD + tx * 8 + 4] = *(float4*)&o[4];
    }
    __syncthreads();

    // ------------------ stage 2: OUT = (H @ W2 + b2) * w --------------------
#pragma unroll
    for (int i = 0; i < 8; i++)
#pragma unroll
        for (int j = 0; j < 4; j++) acc[i][j] = 0ull;

    const float* W2e = W2 + (size_t)e * HID * OUTD;
    for (int k0 = 0; k0 < HID; k0 += 16) {
        *(float4*)&Bs[b_r * 256 + b_c]       = *(const float4*)(W2e + (size_t)(k0 + b_r) * OUTD + b_c);
        *(float4*)&Bs[(b_r + 8) * 256 + b_c] = *(const float4*)(W2e + (size_t)(k0 + b_r + 8) * OUTD + b_c);
        __syncthreads();
#pragma unroll
        for (int kk = 0; kk < 16; kk++) {
            u64 ar2[8];
#pragma unroll
            for (int i = 0; i < 8; i++)
                ar2[i] = bcast2(Hs[(ty * 8 + i) * HPAD + k0 + kk]);  // warp-broadcast
            const u64* bp64 = (const u64*)&Bs[kk * 256 + tx * 8];
            u64 br2[4];
            br2[0] = bp64[0]; br2[1] = bp64[1]; br2[2] = bp64[2]; br2[3] = bp64[3];
#pragma unroll
            for (int i = 0; i < 8; i++)
#pragma unroll
                for (int j = 0; j < 4; j++)
                    ffma2(acc[i][j], ar2[i], br2[j]);
        }
        __syncthreads();
    }

#pragma unroll
    for (int i = 0; i < 8; i++) {
        const int m = ty * 8 + i;
        if (m < cnt) {
            const unsigned ent = (unsigned)s_ent[m];
            const float w = s_w[m];
            float* dst = g_yslots + (size_t)ent * OUTD + tx * 8;
            float o[8];
#pragma unroll
            for (int j = 0; j < 4; j++) {
                float2 v = unpack2(acc[i][j]);
                o[2 * j]     = (v.x + s_b2[tx * 8 + 2 * j]) * w;
                o[2 * j + 1] = (v.y + s_b2[tx * 8 + 2 * j + 1]) * w;
            }
            *(float4*)dst       = *(float4*)&o[0];
            *(float4*)(dst + 4) = *(float4*)&o[4];
        }
    }
}

// ---------------------------------------------------------------------------
// k_combine: y[t] = yslots[2t] + yslots[2t+1]
// ---------------------------------------------------------------------------
__global__ void k_combine(float* __restrict__ y)
{
    const int gi = blockIdx.x * blockDim.x + threadIdx.x;  // float4 index
    const int t  = gi >> 6;          // 64 float4 per row
    const int c4 = (gi & 63) << 2;
    const float4 a = *(const float4*)&g_yslots[((size_t)2 * t)     * OUTD + c4];
    const float4 b = *(const float4*)&g_yslots[((size_t)2 * t + 1) * OUTD + c4];
    float4 o;
    o.x = a.x + b.x; o.y = a.y + b.y; o.z = a.z + b.z; o.w = a.w + b.w;
    *(float4*)&y[(size_t)t * OUTD + c4] = o;
}

// ---------------------------------------------------------------------------
extern "C" void kernel_launch(void* const* d_in, const int* in_sizes, int n_in,
                              void* d_out, int out_size)
{
    const float* x    = (const float*)d_in[0];
    const float* bias = (const float*)d_in[1];
    const float* W1   = (const float*)d_in[2];
    const float* b1   = (const float*)d_in[3];
    const float* W2   = (const float*)d_in[4];
    const float* b2   = (const float*)d_in[5];
    const float* g1   = (const float*)d_in[6];
    const float* gb1  = (const float*)d_in[7];
    const float* g2   = (const float*)d_in[8];
    const float* gb2  = (const float*)d_in[9];
    const float* g3   = (const float*)d_in[10];
    const float* gb3  = (const float*)d_in[11];

    float* y_out = (float*)d_out;
    float* p_out = y_out + (size_t)BATCH * OUTD;

    float *Y1p = nullptr, *Y2p = nullptr;
    cudaGetSymbolAddress((void**)&Y1p, g_Y1);
    cudaGetSymbolAddress((void**)&Y2p, g_Y2);

    cudaFuncSetAttribute(k_expert, cudaFuncAttributeMaxDynamicSharedMemorySize,
                         EXPERT_SMEM);

    k_zero<<<1, 32>>>();

    // gate layer 1: [65536,256] @ [256,1024] -> relu
    k_gemm_bias_relu<<<dim3(GHID / 256, BATCH / 128), 512>>>(
        x, g1, gb1, Y1p, BATCH, GHID, DIM);

    // gate layer 2: [65536,1024] @ [1024,256] -> relu
    k_gemm_bias_relu<<<dim3(DIM / 256, BATCH / 128), 512>>>(
        Y1p, g2, gb2, Y2p, BATCH, DIM, GHID);

    // gate layer 3 + softmax + top-2 + p output
    k_gate3<<<BATCH / 8, 256>>>(Y2p, g3, gb3, p_out);

    k_scan<<<1, 1>>>();
    k_scatter<<<(BATCH * 2) / 256, 256>>>();

    // grouped expert GEMM (upper bound on tiles: 2B/128 + E = 1040)
    k_expert<<<1040, 512, EXPERT_SMEM>>>(x, bias, W1, b1, W2, b2);

    // y = slot0 + slot1
    k_combine<<<(BATCH * 64) / 256, 256>>>(y_out);
}

// round 10
// speedup vs baseline: 1.0096x; 1.0014x over previous
#include <cuda_runtime.h>
#include <math.h>
#include <stdint.h>

// ---------------------------------------------------------------------------
// MoELayer: B=65536 tokens, D=256, E=16 experts, H=256, O=256, TOP_K=2
// out = [ y (B*O floats) | p (B*E floats) ]
// R8: all GEMM inner loops use packed fma.rn.f32x2 (FFMA2) -> 2x fp32 FMA rate
// ---------------------------------------------------------------------------

#define BATCH   65536
#define DIM     256
#define NEXP    16
#define HID     256
#define OUTD    256
#define GHID    1024   // 4*D

typedef unsigned long long u64;

// ---------------- packed f32x2 helpers (sm_103a) -----------------------------
__device__ __forceinline__ u64 bcast2(float x) {
    u64 r; asm("mov.b64 %0, {%1, %1};" : "=l"(r) : "f"(x)); return r;
}
__device__ __forceinline__ void ffma2(u64& d, u64 a, u64 b) {
    asm("fma.rn.f32x2 %0, %1, %2, %0;" : "+l"(d) : "l"(a), "l"(b));
}
__device__ __forceinline__ float2 unpack2(u64 v) {
    float2 f; asm("mov.b64 {%0, %1}, %2;" : "=f"(f.x), "=f"(f.y) : "l"(v)); return f;
}

// ---------------- scratch (device globals; no allocations allowed) ----------
__device__ float    g_Y1[(size_t)BATCH * GHID];    // 256 MB gate hidden 1
__device__ float    g_Y2[(size_t)BATCH * DIM];     //  64 MB gate hidden 2
__device__ float    g_w[BATCH * 2];                // renormalized top-2 weights
__device__ int      g_eidx[BATCH * 2];             // top-2 expert ids
__device__ int      g_counts[NEXP];
__device__ int      g_offsets[NEXP + 1];
__device__ int      g_cursor[NEXP];
__device__ unsigned g_list[BATCH * 2];             // entry = token*2 + slot
__device__ float    g_yslots[(size_t)BATCH * 2 * OUTD];  // 128 MB per-slot out

// ---------------------------------------------------------------------------
__global__ void k_zero() {
    int i = threadIdx.x;
    if (i < NEXP) g_counts[i] = 0;
}

// ---------------------------------------------------------------------------
// Generic fp32 GEMM via FFMA2: C = relu(A[M,K] @ B[K,N] + bias[N])
// tile 128x256, BK=16, 512 threads, 8x8 per thread (accs packed 8x4 f32x2).
// ---------------------------------------------------------------------------
__global__ __launch_bounds__(512, 1)
void k_gemm_bias_relu(const float* __restrict__ A, const float* __restrict__ B,
                      const float* __restrict__ bv, float* __restrict__ C,
                      int M, int N, int K)
{
    __shared__ float As[16 * 128];
    __shared__ float Bs[16 * 256];

    const int tid = threadIdx.x;
    const int tx = tid & 31;        // n-group (0..31) -> 8 cols each
    const int ty = tid >> 5;        // m-group (0..15) -> 8 rows each
    const int m0 = blockIdx.y * 128;
    const int n0 = blockIdx.x * 256;

    const int a_r = tid >> 2;              // 0..127
    const int a_c = (tid & 3) << 2;        // 0,4,8,12
    const int b_r = tid >> 6;              // 0..7
    const int b_c = (tid & 63) << 2;       // 0..252

    const float* Arow = A + (size_t)(m0 + a_r) * K + a_c;
    const float* Bp   = B + (size_t)b_r * N + n0 + b_c;

    u64 acc[8][4];
#pragma unroll
    for (int i = 0; i < 8; i++)
#pragma unroll
        for (int j = 0; j < 4; j++) acc[i][j] = 0ull;

    for (int k0 = 0; k0 < K; k0 += 16) {
        float4 av = *(const float4*)(Arow + k0);
        As[(a_c + 0) * 128 + a_r] = av.x;
        As[(a_c + 1) * 128 + a_r] = av.y;
        As[(a_c + 2) * 128 + a_r] = av.z;
        As[(a_c + 3) * 128 + a_r] = av.w;
        *(float4*)&Bs[b_r * 256 + b_c]       = *(const float4*)(Bp + (size_t)k0 * N);
        *(float4*)&Bs[(b_r + 8) * 256 + b_c] = *(const float4*)(Bp + (size_t)(k0 + 8) * N);
        __syncthreads();

#pragma unroll
        for (int kk = 0; kk < 16; kk++) {
            float ar[8];
            *(float4*)&ar[0] = *(const float4*)&As[kk * 128 + ty * 8];
            *(float4*)&ar[4] = *(const float4*)&As[kk * 128 + ty * 8 + 4];
            u64 ar2[8];
#pragma unroll
            for (int i = 0; i < 8; i++) ar2[i] = bcast2(ar[i]);
            const u64* bp64 = (const u64*)&Bs[kk * 256 + tx * 8];
            u64 br2[4];
            br2[0] = bp64[0]; br2[1] = bp64[1]; br2[2] = bp64[2]; br2[3] = bp64[3];
#pragma unroll
            for (int i = 0; i < 8; i++)
#pragma unroll
                for (int j = 0; j < 4; j++)
                    ffma2(acc[i][j], ar2[i], br2[j]);
        }
        __syncthreads();
    }

    // epilogue: + bias, relu, store
    float bb[8];
#pragma unroll
    for (int j = 0; j < 8; j++) bb[j] = bv[n0 + tx * 8 + j];
#pragma unroll
    for (int i = 0; i < 8; i++) {
        const int m = m0 + ty * 8 + i;
        float* crow = C + (size_t)m * N + n0 + tx * 8;
        float o[8];
#pragma unroll
        for (int j = 0; j < 4; j++) {
            float2 v = unpack2(acc[i][j]);
            o[2 * j]     = fmaxf(v.x + bb[2 * j], 0.f);
            o[2 * j + 1] = fmaxf(v.y + bb[2 * j + 1], 0.f);
        }
        *(float4*)crow       = *(float4*)&o[0];
        *(float4*)(crow + 4) = *(float4*)&o[4];
    }
}

// ---------------------------------------------------------------------------
// k_gate3: one warp per token. logits = Y2 @ g3 + gb3; softmax(T=1);
// top-2 on logits; renormalize; sparse p to output; histogram counts.
// ---------------------------------------------------------------------------
__global__ void k_gate3(const float* __restrict__ Y2, const float* __restrict__ g3,
                        const float* __restrict__ gb3, float* __restrict__ p_out)
{
    __shared__ float sg3[NEXP * DIM];   // transposed: [e][k]
    __shared__ float sgb3[NEXP];
    for (int i = threadIdx.x; i < NEXP * DIM; i += blockDim.x) {
        int k = i >> 4, e = i & 15;
        sg3[e * DIM + k] = g3[i];
    }
    if (threadIdx.x < NEXP) sgb3[threadIdx.x] = gb3[threadIdx.x];
    __syncthreads();

    const int gw   = (blockIdx.x * blockDim.x + threadIdx.x) >> 5;  // token
    const int lane = threadIdx.x & 31;

    const float* y = Y2 + (size_t)gw * DIM;
    float yv[8];
#pragma unroll
    for (int i = 0; i < 8; i++) yv[i] = y[lane + 32 * i];

    float l[NEXP];
#pragma unroll
    for (int e = 0; e < NEXP; e++) {
        float s = 0.f;
#pragma unroll
        for (int i = 0; i < 8; i++)
            s = fmaf(yv[i], sg3[e * DIM + lane + 32 * i], s);
        l[e] = s;
    }
#pragma unroll
    for (int off = 16; off > 0; off >>= 1)
#pragma unroll
        for (int e = 0; e < NEXP; e++)
            l[e] += __shfl_xor_sync(0xffffffffu, l[e], off);
#pragma unroll
    for (int e = 0; e < NEXP; e++) l[e] += sgb3[e];

    int i1 = 0; float t1 = l[0];
#pragma unroll
    for (int e = 1; e < NEXP; e++) if (l[e] > t1) { t1 = l[e]; i1 = e; }
    int i2 = -1; float t2 = -INFINITY;
#pragma unroll
    for (int e = 0; e < NEXP; e++) if (e != i1 && l[e] > t2) { t2 = l[e]; i2 = e; }

    const float mx = t1;
    float se = 0.f;
#pragma unroll
    for (int e = 0; e < NEXP; e++) se += expf(l[e] - mx);
    const float inv = 1.f / se;
    const float v1 = expf(t1 - mx) * inv;
    const float v2 = expf(t2 - mx) * inv;
    const float dn = 1.f / (v1 + v2 + 1e-9f);
    const float w0 = v1 * dn, w1 = v2 * dn;

    if (lane < NEXP) {
        float pv = (lane == i1) ? w0 : ((lane == i2) ? w1 : 0.f);
        p_out[(size_t)gw * NEXP + lane] = pv;
    }
    if (lane == 0) {
        g_w[gw * 2 + 0]    = w0;
        g_w[gw * 2 + 1]    = w1;
        g_eidx[gw * 2 + 0] = i1;
        g_eidx[gw * 2 + 1] = i2;
        atomicAdd(&g_counts[i1], 1);
        atomicAdd(&g_counts[i2], 1);
    }
}

// ---------------------------------------------------------------------------
__global__ void k_scan() {
    if (threadIdx.x == 0) {
        int acc = 0;
        for (int i = 0; i < NEXP; i++) {
            g_offsets[i] = acc;
            acc += g_counts[i];
            g_cursor[i] = 0;
        }
        g_offsets[NEXP] = acc;
    }
}

__global__ void k_scatter() {
    int i = blockIdx.x * blockDim.x + threadIdx.x;   // entry = token*2 + slot
    if (i >= BATCH * 2) return;
    int e = g_eidx[i];
    int pos = atomicAdd(&g_cursor[e], 1);
    g_list[g_offsets[e] + pos] = (unsigned)i;
}

// ---------------------------------------------------------------------------
// k_expert: grouped expert GEMM (FFMA2). Each block = 128-row tile of one expert.
//   stage 1: H[128,256] = relu((gather(x)+bias[e]) @ W1[e] + b1[e])  -> smem
//   stage 2: OUT[128,256] = (H @ W2[e] + b2[e]) * w  -> g_yslots rows
// ---------------------------------------------------------------------------
#define HPAD 260
#define EXPERT_SMEM ((128*HPAD + 16*128 + 16*256 + 3*256 + 128) * 4 + 128 * 4)

__global__ __launch_bounds__(512, 1)
void k_expert(const float* __restrict__ x, const float* __restrict__ bias,
              const float* __restrict__ W1, const float* __restrict__ b1,
              const float* __restrict__ W2, const float* __restrict__ b2)
{
    extern __shared__ float sm[];
    float* Hs     = sm;                         // 128*HPAD
    float* As     = Hs + 128 * HPAD;            // 16*128
    float* Bs     = As + 16 * 128;              // 16*256
    float* s_bias = Bs + 16 * 256;              // 256
    float* s_b1   = s_bias + 256;               // 256
    float* s_b2   = s_b1 + 256;                 // 256
    float* s_w    = s_b2 + 256;                 // 128
    int*   s_ent  = (int*)(s_w + 128);          // 128
    __shared__ int s_meta[3];

    const int tid = threadIdx.x;

    if (tid == 0) {
        int bid = blockIdx.x, acc = 0, e = -1, row0 = 0, cnt = 0;
        for (int i = 0; i < NEXP; i++) {
            int c  = g_counts[i];
            int nt = (c + 127) >> 7;
            if (e < 0 && bid < acc + nt) {
                int tt = bid - acc;
                e = i;
                row0 = g_offsets[i] + tt * 128;
                cnt  = c - tt * 128;
                if (cnt > 128) cnt = 128;
            }
            acc += nt;
        }
        s_meta[0] = e; s_meta[1] = row0; s_meta[2] = cnt;
    }
    __syncthreads();

    const int e = s_meta[0];
    if (e < 0) return;
    const int row0 = s_meta[1];
    const int cnt  = s_meta[2];

    if (tid < 128) {
        unsigned ent = g_list[row0 + ((tid < cnt) ? tid : 0)];
        s_ent[tid] = (int)ent;
        s_w[tid]   = g_w[ent];
    }
    for (int i = tid; i < 256; i += 512) {
        s_bias[i] = bias[e * 256 + i];
        s_b1[i]   = b1[e * 256 + i];
        s_b2[i]   = b2[e * 256 + i];
    }
    __syncthreads();

    const int tx = tid & 31, ty = tid >> 5;
    const int a_r = tid >> 2, a_c = (tid & 3) << 2;
    const int b_r = tid >> 6, b_c = (tid & 63) << 2;

    const int tok = s_ent[a_r] >> 1;
    const float* xrow = x + (size_t)tok * DIM;

    u64 acc[8][4];
#pragma unroll
    for (int i = 0; i < 8; i++)
#pragma unroll
        for (int j = 0; j < 4; j++) acc[i][j] = 0ull;

    // ------------------ stage 1: H = relu((x+bias) @ W1 + b1) ---------------
    const float* W1e = W1 + (size_t)e * DIM * HID;
    for (int k0 = 0; k0 < DIM; k0 += 16) {
        float4 av = *(const float4*)(xrow + k0 + a_c);
        float4 bb = *(const float4*)(s_bias + k0 + a_c);
        As[(a_c + 0) * 128 + a_r] = av.x + bb.x;
        As[(a_c + 1) * 128 + a_r] = av.y + bb.y;
        As[(a_c + 2) * 128 + a_r] = av.z + bb.z;
        As[(a_c + 3) * 128 + a_r] = av.w + bb.w;
        *(float4*)&Bs[b_r * 256 + b_c]       = *(const float4*)(W1e + (size_t)(k0 + b_r) * HID + b_c);
        *(float4*)&Bs[(b_r + 8) * 256 + b_c] = *(const float4*)(W1e + (size_t)(k0 + b_r + 8) * HID + b_c);
        __syncthreads();
#pragma unroll
        for (int kk = 0; kk < 16; kk++) {
            float ar[8];
            *(float4*)&ar[0] = *(const float4*)&As[kk * 128 + ty * 8];
            *(float4*)&ar[4] = *(const float4*)&As[kk * 128 + ty * 8 + 4];
            u64 ar2[8];
#pragma unroll
            for (int i = 0; i < 8; i++) ar2[i] = bcast2(ar[i]);
            const u64* bp64 = (const u64*)&Bs[kk * 256 + tx * 8];
            u64 br2[4];
            br2[0] = bp64[0]; br2[1] = bp64[1]; br2[2] = bp64[2]; br2[3] = bp64[3];
#pragma unroll
            for (int i = 0; i < 8; i++)
#pragma unroll
                for (int j = 0; j < 4; j++)
                    ffma2(acc[i][j], ar2[i], br2[j]);
        }
        __syncthreads();
    }
    // write H tile to smem (relu + b1)
#pragma unroll
    for (int i = 0; i < 8; i++) {
        const int m = ty * 8 + i;
        float o[8];
#pragma unroll
        for (int j = 0; j < 4; j++) {
            float2 v = unpack2(acc[i][j]);
            o[2 * j]     = fmaxf(v.x + s_b1[tx * 8 + 2 * j], 0.f);
            o[2 * j + 1] = fmaxf(v.y + s_b1[tx * 8 + 2 * j + 1], 0.f);
        }
        *(float4*)&Hs[m * HPAD + tx * 8]     = *(float4*)&o[0];
        *(float4*)&Hs[m * HPAD + tx * 8 + 4] = *(float4*)&o[4];
    }
    __syncthreads();

    // ------------------ stage 2: OUT = (H @ W2 + b2) * w --------------------
#pragma unroll
    for (int i = 0; i < 8; i++)
#pragma unroll
        for (int j = 0; j < 4; j++) acc[i][j] = 0ull;

    const float* W2e = W2 + (size_t)e * HID * OUTD;
    for (int k0 = 0; k0 < HID; k0 += 16) {
        *(float4*)&Bs[b_r * 256 + b_c]       = *(const float4*)(W2e + (size_t)(k0 + b_r) * OUTD + b_c);
        *(float4*)&Bs[(b_r + 8) * 256 + b_c] = *(const float4*)(W2e + (size_t)(k0 + b_r + 8) * OUTD + b_c);
        __syncthreads();
#pragma unroll
        for (int kk = 0; kk < 16; kk++) {
            u64 ar2[8];
#pragma unroll
            for (int i = 0; i < 8; i++)
                ar2[i] = bcast2(Hs[(ty * 8 + i) * HPAD + k0 + kk]);  // warp-broadcast
            const u64* bp64 = (const u64*)&Bs[kk * 256 + tx * 8];
            u64 br2[4];
            br2[0] = bp64[0]; br2[1] = bp64[1]; br2[2] = bp64[2]; br2[3] = bp64[3];
#pragma unroll
            for (int i = 0; i < 8; i++)
#pragma unroll
                for (int j = 0; j < 4; j++)
                    ffma2(acc[i][j], ar2[i], br2[j]);
        }
        __syncthreads();
    }

#pragma unroll
    for (int i = 0; i < 8; i++) {
        const int m = ty * 8 + i;
        if (m < cnt) {
            const unsigned ent = (unsigned)s_ent[m];
            const float w = s_w[m];
            float* dst = g_yslots + (size_t)ent * OUTD + tx * 8;
            float o[8];
#pragma unroll
            for (int j = 0; j < 4; j++) {
                float2 v = unpack2(acc[i][j]);
                o[2 * j]     = (v.x + s_b2[tx * 8 + 2 * j]) * w;
                o[2 * j + 1] = (v.y + s_b2[tx * 8 + 2 * j + 1]) * w;
            }
            *(float4*)dst       = *(float4*)&o[0];
            *(float4*)(dst + 4) = *(float4*)&o[4];
        }
    }
}

// ---------------------------------------------------------------------------
// k_combine: y[t] = yslots[2t] + yslots[2t+1]
// ---------------------------------------------------------------------------
__global__ void k_combine(float* __restrict__ y)
{
    const int gi = blockIdx.x * blockDim.x + threadIdx.x;  // float4 index
    const int t  = gi >> 6;          // 64 float4 per row
    const int c4 = (gi & 63) << 2;
    const float4 a = *(const float4*)&g_yslots[((size_t)2 * t)     * OUTD + c4];
    const float4 b = *(const float4*)&g_yslots[((size_t)2 * t + 1) * OUTD + c4];
    float4 o;
    o.x = a.x + b.x; o.y = a.y + b.y; o.z = a.z + b.z; o.w = a.w + b.w;
    *(float4*)&y[(size_t)t * OUTD + c4] = o;
}

// ---------------------------------------------------------------------------
extern "C" void kernel_launch(void* const* d_in, const int* in_sizes, int n_in,
                              void* d_out, int out_size)
{
    const float* x    = (const float*)d_in[0];
    const float* bias = (const float*)d_in[1];
    const float* W1   = (const float*)d_in[2];
    const float* b1   = (const float*)d_in[3];
    const float* W2   = (const float*)d_in[4];
    const float* b2   = (const float*)d_in[5];
    const float* g1   = (const float*)d_in[6];
    const float* gb1  = (const float*)d_in[7];
    const float* g2   = (const float*)d_in[8];
    const float* gb2  = (const float*)d_in[9];
    const float* g3   = (const float*)d_in[10];
    const float* gb3  = (const float*)d_in[11];

    float* y_out = (float*)d_out;
    float* p_out = y_out + (size_t)BATCH * OUTD;

    float *Y1p = nullptr, *Y2p = nullptr;
    cudaGetSymbolAddress((void**)&Y1p, g_Y1);
    cudaGetSymbolAddress((void**)&Y2p, g_Y2);

    cudaFuncSetAttribute(k_expert, cudaFuncAttributeMaxDynamicSharedMemorySize,
                         EXPERT_SMEM);

    k_zero<<<1, 32>>>();

    // gate layer 1: [65536,256] @ [256,1024] -> relu
    k_gemm_bias_relu<<<dim3(GHID / 256, BATCH / 128), 512>>>(
        x, g1, gb1, Y1p, BATCH, GHID, DIM);

    // gate layer 2: [65536,1024] @ [1024,256] -> relu
    k_gemm_bias_relu<<<dim3(DIM / 256, BATCH / 128), 512>>>(
        Y1p, g2, gb2, Y2p, BATCH, DIM, GHID);

    // gate layer 3 + softmax + top-2 + p output
    k_gate3<<<BATCH / 8, 256>>>(Y2p, g3, gb3, p_out);

    k_scan<<<1, 1>>>();
    k_scatter<<<(BATCH * 2) / 256, 256>>>();

    // grouped expert GEMM (upper bound on tiles: 2B/128 + E = 1040)
    k_expert<<<1040, 512, EXPERT_SMEM>>>(x, bias, W1, b1, W2, b2);

    // y = slot0 + slot1
    k_combine<<<(BATCH * 64) / 256, 256>>>(y_out);
}